// round 1
// baseline (speedup 1.0000x reference)
#include <cuda_runtime.h>
#include <cstdint>

#define N_NODES 50000
#define N_EDGES_MAX 400000
#define F0 600
#define F1 628
#define F1P 632   /* padded so K%8==0 for GEMM2 */
#define F2 64

// ---------------- scratch (static __device__ allocations) ----------------
__device__ float g_dinv[N_NODES];
__device__ float g_G  [(size_t)N_NODES * F1];
__device__ float g_ACC[(size_t)N_NODES * F1];
__device__ float g_out1[(size_t)N_NODES * F1P];
__device__ float g_W2p[F1P * F2];
__device__ float g_G2 [(size_t)N_NODES * F2];
__device__ float g_ACC2[(size_t)N_NODES * F2];

// ---------------- degree / dinv ----------------
__global__ void k_deg_init(float* deg, int n) {
    int i = blockIdx.x * blockDim.x + threadIdx.x;
    if (i < n) deg[i] = 1.0f;              // self loop
}
__global__ void k_deg_count(float* deg, const int* __restrict__ dst, int e) {
    int i = blockIdx.x * blockDim.x + threadIdx.x;
    if (i < e) atomicAdd(&deg[dst[i]], 1.0f);
}
__global__ void k_deg_finish(float* deg, int n) {
    int i = blockIdx.x * blockDim.x + threadIdx.x;
    if (i < n) deg[i] = rsqrtf(deg[i]);    // deg >= 1 always
}

// ---------------- pad W2 to [F1P, F2] ----------------
__global__ void k_pad_w2(const float* __restrict__ W2, float* __restrict__ W2p) {
    int idx = blockIdx.x * blockDim.x + threadIdx.x;
    if (idx >= F1P * F2) return;
    int r = idx / F2;
    W2p[idx] = (r < F1) ? W2[idx] : 0.0f;
}

// ---------------- SGEMM: C[r,c] = rowScale[r] * sum_k A[r,k]*B[k,c] ----------------
// K must be a multiple of BK. M,N guarded.
template <int BM, int BN, int BK, int TM, int TN>
__global__ __launch_bounds__((BM / TM) * (BN / TN), 1)
void sgemm_rowscale(const float* __restrict__ A, const float* __restrict__ B,
                    float* __restrict__ C, const float* __restrict__ rowScale,
                    int M, int N, int K, int lda, int ldb, int ldc) {
    constexpr int NT = (BM / TM) * (BN / TN);
    __shared__ float As[BK][BM];
    __shared__ float Bs[BK][BN];

    const int tid = threadIdx.x;
    const int tx = tid % (BN / TN);
    const int ty = tid / (BN / TN);
    const int rowBase = blockIdx.y * BM;
    const int colBase = blockIdx.x * BN;

    float acc[TM][TN];
#pragma unroll
    for (int i = 0; i < TM; i++)
#pragma unroll
        for (int j = 0; j < TN; j++) acc[i][j] = 0.0f;

    for (int k0 = 0; k0 < K; k0 += BK) {
        // load A tile (BM x BK) transposed into As
#pragma unroll
        for (int idx = tid; idx < BM * BK; idx += NT) {
            int r = idx / BK, c = idx % BK;
            int gr = rowBase + r;
            As[c][r] = (gr < M) ? A[(size_t)gr * lda + k0 + c] : 0.0f;
        }
        // load B tile (BK x BN)
#pragma unroll
        for (int idx = tid; idx < BK * BN; idx += NT) {
            int r = idx / BN, c = idx % BN;
            int gc = colBase + c;
            Bs[r][c] = (gc < N) ? B[(size_t)(k0 + r) * ldb + gc] : 0.0f;
        }
        __syncthreads();

#pragma unroll
        for (int kk = 0; kk < BK; kk++) {
            float a[TM], b[TN];
#pragma unroll
            for (int i = 0; i < TM; i++) a[i] = As[kk][ty * TM + i];
#pragma unroll
            for (int j = 0; j < TN; j++) b[j] = Bs[kk][tx * TN + j];
#pragma unroll
            for (int i = 0; i < TM; i++)
#pragma unroll
                for (int j = 0; j < TN; j++) acc[i][j] += a[i] * b[j];
        }
        __syncthreads();
    }

#pragma unroll
    for (int i = 0; i < TM; i++) {
        int row = rowBase + ty * TM + i;
        if (row >= M) continue;
        float s = rowScale[row];
#pragma unroll
        for (int j = 0; j < TN; j++) {
            int col = colBase + tx * TN + j;
            if (col < N) C[(size_t)row * ldc + col] = s * acc[i][j];
        }
    }
}

// ---------------- float4 copy ----------------
__global__ void k_copy_f4(const float4* __restrict__ src, float4* __restrict__ dst, int n4) {
    int i = blockIdx.x * blockDim.x + threadIdx.x;
    if (i < n4) dst[i] = src[i];
}

// ---------------- edge scatter (628-dim): one warp per edge ----------------
__global__ void k_scatter628(const float* __restrict__ G, float* __restrict__ ACC,
                             const int* __restrict__ src, const int* __restrict__ dst, int E) {
    int gw = (blockIdx.x * blockDim.x + threadIdx.x) >> 5;
    if (gw >= E) return;
    int lane = threadIdx.x & 31;
    int s = __ldg(&src[gw]);
    int d = __ldg(&dst[gw]);
    const float4* g = (const float4*)(G + (size_t)s * F1);
    float4* a = (float4*)(ACC + (size_t)d * F1);
    const int nf4 = F1 / 4;  // 157
#pragma unroll
    for (int i = lane; i < nf4; i += 32) {
        float4 v = g[i];
        atomicAdd(&a[i], v);  // f32x4 reduction, sm_90+
    }
}

// ---------------- edge scatter (64-dim): 16 threads per edge ----------------
__global__ void k_scatter64(const float* __restrict__ G, float* __restrict__ ACC,
                            const int* __restrict__ src, const int* __restrict__ dst, int E) {
    int gid = blockIdx.x * blockDim.x + threadIdx.x;
    int e = gid >> 4;
    if (e >= E) return;
    int t = gid & 15;
    int s = __ldg(&src[e]);
    int d = __ldg(&dst[e]);
    float4 v = ((const float4*)(G + (size_t)s * F2))[t];
    atomicAdd(&((float4*)(ACC + (size_t)d * F2))[t], v);
}

// ---------------- finalize layer 1: out1 = relu(dinv*ACC + b1), pad to F1P ----------------
__global__ void k_final1(const float* __restrict__ ACC, const float* __restrict__ dinv,
                         const float* __restrict__ b1, float* __restrict__ out1) {
    int idx = blockIdx.x * blockDim.x + threadIdx.x;
    if (idx >= N_NODES * F1P) return;
    int r = idx / F1P;
    int c = idx - r * F1P;
    float v = 0.0f;
    if (c < F1) v = fmaxf(fmaf(dinv[r], ACC[(size_t)r * F1 + c], b1[c]), 0.0f);
    out1[idx] = v;
}

// ---------------- finalize layer 2: Z = dinv*ACC2 + b2 ----------------
__global__ void k_final2(const float* __restrict__ ACC2, const float* __restrict__ dinv,
                         const float* __restrict__ b2, float* __restrict__ Z) {
    int idx = blockIdx.x * blockDim.x + threadIdx.x;
    if (idx >= N_NODES * F2) return;
    int r = idx >> 6;
    int c = idx & 63;
    Z[idx] = fmaf(dinv[r], ACC2[idx], b2[c]);
}

// ---------------- decode: logits[e] = dot(Z[src], Z[dst]) over 64 dims ----------------
__global__ void k_decode(const float* __restrict__ Z, const int* __restrict__ src,
                         const int* __restrict__ dst, float* __restrict__ out, int E) {
    int gid = blockIdx.x * blockDim.x + threadIdx.x;
    int e = gid >> 3;
    if (e >= E) return;
    int t = gid & 7;
    int s = __ldg(&src[e]);
    int d = __ldg(&dst[e]);
    const float4* zs = (const float4*)(Z + (size_t)s * F2);
    const float4* zd = (const float4*)(Z + (size_t)d * F2);
    float sum = 0.0f;
#pragma unroll
    for (int i = t; i < 16; i += 8) {
        float4 a = zs[i];
        float4 b = zd[i];
        sum += a.x * b.x + a.y * b.y + a.z * b.z + a.w * b.w;
    }
#pragma unroll
    for (int off = 4; off; off >>= 1) sum += __shfl_down_sync(0xffffffffu, sum, off, 8);
    if (t == 0) out[e] = sum;
}

// ---------------- launch ----------------
extern "C" void kernel_launch(void* const* d_in, const int* in_sizes, int n_in,
                              void* d_out, int out_size) {
    const float* x  = (const float*)d_in[0];
    const int*   ei = (const int*)d_in[1];
    const float* W1 = (const float*)d_in[2];
    const float* b1 = (const float*)d_in[3];
    const float* W2 = (const float*)d_in[4];
    const float* b2 = (const float*)d_in[5];
    float* logits = (float*)d_out;

    const int E = in_sizes[1] / 2;
    const int M = N_NODES;
    const int* src = ei;
    const int* dst = ei + E;

    float *dinv, *G, *ACC, *out1, *W2p, *G2, *ACC2;
    cudaGetSymbolAddress((void**)&dinv, g_dinv);
    cudaGetSymbolAddress((void**)&G, g_G);
    cudaGetSymbolAddress((void**)&ACC, g_ACC);
    cudaGetSymbolAddress((void**)&out1, g_out1);
    cudaGetSymbolAddress((void**)&W2p, g_W2p);
    cudaGetSymbolAddress((void**)&G2, g_G2);
    cudaGetSymbolAddress((void**)&ACC2, g_ACC2);

    // --- degrees -> dinv ---
    k_deg_init<<<(M + 255) / 256, 256>>>(dinv, M);
    k_deg_count<<<(E + 255) / 256, 256>>>(dinv, dst, E);
    k_deg_finish<<<(M + 255) / 256, 256>>>(dinv, M);

    // --- pad W2 ---
    k_pad_w2<<<(F1P * F2 + 255) / 256, 256>>>(W2, W2p);

    // --- layer 1: G = dinv ⊙ (x @ W1) ---
    {
        dim3 grid((F1 + 127) / 128, (M + 127) / 128);
        sgemm_rowscale<128, 128, 8, 8, 8><<<grid, 256>>>(
            x, W1, G, dinv, M, F1, F0, F0, F1, F1);
    }
    // ACC = G (self-loop term)
    {
        int n4 = (int)((size_t)M * F1 / 4);
        k_copy_f4<<<(n4 + 255) / 256, 256>>>((const float4*)G, (float4*)ACC, n4);
    }
    // edge aggregation
    k_scatter628<<<(E * 32 + 255) / 256, 256>>>(G, ACC, src, dst, E);
    // out1 = relu(dinv*ACC + b1), padded
    k_final1<<<(M * F1P + 255) / 256, 256>>>(ACC, dinv, b1, out1);

    // --- layer 2: G2 = dinv ⊙ (out1 @ W2p) ---
    {
        dim3 grid(1, (M + 127) / 128);
        sgemm_rowscale<128, 64, 8, 8, 4><<<grid, 256>>>(
            out1, W2p, G2, dinv, M, F2, F1P, F1P, F2, F2);
    }
    {
        int n4 = (int)((size_t)M * F2 / 4);
        k_copy_f4<<<(n4 + 255) / 256, 256>>>((const float4*)G2, (float4*)ACC2, n4);
    }
    k_scatter64<<<(E * 16 + 255) / 256, 256>>>(G2, ACC2, src, dst, E);
    // Z stored back into G2's buffer? keep separate: reuse g_out1 head as Z storage is fine,
    // but clearer: write Z into ACC2's finalize output -> reuse G2 buffer (no longer needed).
    k_final2<<<(M * F2 + 255) / 256, 256>>>(ACC2, dinv, b2, G2);

    // --- decode ---
    k_decode<<<(E * 8 + 255) / 256, 256>>>(G2, src, dst, logits, E);
}

// round 2
// speedup vs baseline: 2.3597x; 2.3597x over previous
#include <cuda_runtime.h>
#include <cstdint>

#define N_NODES 50000
#define F0 600
#define F1 628
#define F2 64

// ---------------- scratch (static __device__ allocations) ----------------
__device__ float g_dinv[N_NODES];
__device__ float g_G  [(size_t)N_NODES * F1];
__device__ float g_ACC[(size_t)N_NODES * F1];
__device__ float g_out1[(size_t)N_NODES * F1];
__device__ float g_G2 [(size_t)N_NODES * F2];
__device__ float g_ACC2[(size_t)N_NODES * F2];

// ---------------- degree / dinv ----------------
__global__ void k_deg_init(float* deg, int n) {
    int i = blockIdx.x * blockDim.x + threadIdx.x;
    if (i < n) deg[i] = 1.0f;              // self loop
}
__global__ void k_deg_count(float* deg, const int* __restrict__ dst, int e) {
    int i = blockIdx.x * blockDim.x + threadIdx.x;
    if (i < e) atomicAdd(&deg[dst[i]], 1.0f);
}
__global__ void k_deg_finish(float* deg, int n) {
    int i = blockIdx.x * blockDim.x + threadIdx.x;
    if (i < n) deg[i] = rsqrtf(deg[i]);    // deg >= 1 always
}

// ---------------- tf32 helpers ----------------
__device__ __forceinline__ float to_tf32(float x) {
    uint32_t u;
    asm("cvt.rna.tf32.f32 %0, %1;" : "=r"(u) : "f"(x));
    return __uint_as_float(u);
}
__device__ __forceinline__ void mma_16x8x8(float* d, const float* a, const float* b) {
    asm volatile(
        "mma.sync.aligned.m16n8k8.row.col.f32.tf32.tf32.f32 "
        "{%0,%1,%2,%3}, {%4,%5,%6,%7}, {%8,%9}, {%0,%1,%2,%3};"
        : "+f"(d[0]), "+f"(d[1]), "+f"(d[2]), "+f"(d[3])
        : "r"(__float_as_uint(a[0])), "r"(__float_as_uint(a[1])),
          "r"(__float_as_uint(a[2])), "r"(__float_as_uint(a[3])),
          "r"(__float_as_uint(b[0])), "r"(__float_as_uint(b[1])));
}

// ---------------- TF32 MMA GEMM: C = C2 = rowScale ⊙ (A@B) ----------------
// A [M,K] row-major, B [K,N] row-major, C/C2 [M,N] row-major.
// Zero-fill guards on K and N edges (K%4==0, N%4==0 required).
template <int BM, int BN, int BK, int WM, int WN>
__global__ __launch_bounds__((BM / WM) * (BN / WN) * 32, 1)
void gemm_tf32(const float* __restrict__ A, const float* __restrict__ B,
               float* __restrict__ C, float* __restrict__ C2,
               const float* __restrict__ rowScale,
               int M, int N, int K, int lda, int ldb, int ldc) {
    constexpr int WARPS_M = BM / WM;
    constexpr int WARPS_N = BN / WN;
    constexpr int NTHREADS = WARPS_M * WARPS_N * 32;
    constexpr int MT = WM / 16;
    constexpr int NT = WN / 8;
    constexpr int LDA_S = BK + 4;    // 36: fragment reads conflict-free
    constexpr int LDB_S = BN + 8;    // banks 8*tig+gid distinct

    __shared__ float As[BM][LDA_S];
    __shared__ float Bs[BK][LDB_S];

    const int tid = threadIdx.x;
    const int lane = tid & 31;
    const int warp = tid >> 5;
    const int warpM = warp / WARPS_N;
    const int warpN = warp % WARPS_N;
    const int gid = lane >> 2;   // 0..7
    const int tig = lane & 3;    // 0..3
    const int rowBase = blockIdx.y * BM;
    const int colBase = blockIdx.x * BN;

    float acc[MT][NT][4];
#pragma unroll
    for (int i = 0; i < MT; i++)
#pragma unroll
        for (int j = 0; j < NT; j++)
#pragma unroll
            for (int q = 0; q < 4; q++) acc[i][j][q] = 0.0f;

    constexpr int LA = (BM * BK / 4) / NTHREADS;   // float4s per thread (A)
    constexpr int LB = (BK * BN / 4) / NTHREADS;   // float4s per thread (B)

    for (int k0 = 0; k0 < K; k0 += BK) {
        // --- A tile: [BM][BK], row-major in smem ---
#pragma unroll
        for (int i = 0; i < LA; i++) {
            int f = tid + i * NTHREADS;
            int row = f / (BK / 4);
            int k = (f % (BK / 4)) * 4;
            int grow = rowBase + row;
            int gk = k0 + k;
            float4 v = make_float4(0.f, 0.f, 0.f, 0.f);
            if (grow < M && gk < K)
                v = *(const float4*)(A + (size_t)grow * lda + gk);
            v.x = to_tf32(v.x); v.y = to_tf32(v.y);
            v.z = to_tf32(v.z); v.w = to_tf32(v.w);
            *(float4*)(&As[row][k]) = v;
        }
        // --- B tile: [BK][BN], k-major in smem ---
#pragma unroll
        for (int i = 0; i < LB; i++) {
            int f = tid + i * NTHREADS;
            int krow = f / (BN / 4);
            int n = (f % (BN / 4)) * 4;
            int gk = k0 + krow;
            int gcol = colBase + n;
            float4 v = make_float4(0.f, 0.f, 0.f, 0.f);
            if (gk < K && gcol < N)
                v = *(const float4*)(B + (size_t)gk * ldb + gcol);
            v.x = to_tf32(v.x); v.y = to_tf32(v.y);
            v.z = to_tf32(v.z); v.w = to_tf32(v.w);
            *(float4*)(&Bs[krow][n]) = v;
        }
        __syncthreads();

#pragma unroll
        for (int kk = 0; kk < BK / 8; kk++) {
            const int kb = kk * 8;
            float a[MT][4];
            float b[NT][2];
#pragma unroll
            for (int mt = 0; mt < MT; mt++) {
                int r = warpM * WM + mt * 16 + gid;
                a[mt][0] = As[r][kb + tig];
                a[mt][1] = As[r + 8][kb + tig];
                a[mt][2] = As[r][kb + tig + 4];
                a[mt][3] = As[r + 8][kb + tig + 4];
            }
#pragma unroll
            for (int nt = 0; nt < NT; nt++) {
                int c = warpN * WN + nt * 8 + gid;
                b[nt][0] = Bs[kb + tig][c];
                b[nt][1] = Bs[kb + tig + 4][c];
            }
#pragma unroll
            for (int mt = 0; mt < MT; mt++)
#pragma unroll
                for (int nt = 0; nt < NT; nt++)
                    mma_16x8x8(acc[mt][nt], a[mt], b[nt]);
        }
        __syncthreads();
    }

    // --- epilogue: C = C2 = rowScale * acc ---
#pragma unroll
    for (int mt = 0; mt < MT; mt++) {
        int r0 = rowBase + warpM * WM + mt * 16 + gid;
        int r1 = r0 + 8;
        float s0 = (r0 < M) ? __ldg(&rowScale[r0]) : 0.0f;
        float s1 = (r1 < M) ? __ldg(&rowScale[r1]) : 0.0f;
#pragma unroll
        for (int nt = 0; nt < NT; nt++) {
            int c0 = colBase + warpN * WN + nt * 8 + 2 * tig;
            if (c0 >= N) continue;
            if (r0 < M) {
                float2 v = make_float2(s0 * acc[mt][nt][0], s0 * acc[mt][nt][1]);
                *(float2*)(C  + (size_t)r0 * ldc + c0) = v;
                *(float2*)(C2 + (size_t)r0 * ldc + c0) = v;
            }
            if (r1 < M) {
                float2 v = make_float2(s1 * acc[mt][nt][2], s1 * acc[mt][nt][3]);
                *(float2*)(C  + (size_t)r1 * ldc + c0) = v;
                *(float2*)(C2 + (size_t)r1 * ldc + c0) = v;
            }
        }
    }
}

// ---------------- edge scatter (628-dim): one warp per edge ----------------
__global__ void k_scatter628(const float* __restrict__ G, float* __restrict__ ACC,
                             const int* __restrict__ src, const int* __restrict__ dst, int E) {
    int gw = (blockIdx.x * blockDim.x + threadIdx.x) >> 5;
    if (gw >= E) return;
    int lane = threadIdx.x & 31;
    int s = __ldg(&src[gw]);
    int d = __ldg(&dst[gw]);
    const float4* g = (const float4*)(G + (size_t)s * F1);
    float4* a = (float4*)(ACC + (size_t)d * F1);
    const int nf4 = F1 / 4;  // 157
#pragma unroll
    for (int i = lane; i < nf4; i += 32) {
        float4 v = g[i];
        atomicAdd(&a[i], v);
    }
}

// ---------------- edge scatter (64-dim): 16 threads per edge ----------------
__global__ void k_scatter64(const float* __restrict__ G, float* __restrict__ ACC,
                            const int* __restrict__ src, const int* __restrict__ dst, int E) {
    int gid = blockIdx.x * blockDim.x + threadIdx.x;
    int e = gid >> 4;
    if (e >= E) return;
    int t = gid & 15;
    int s = __ldg(&src[e]);
    int d = __ldg(&dst[e]);
    float4 v = ((const float4*)(G + (size_t)s * F2))[t];
    atomicAdd(&((float4*)(ACC + (size_t)d * F2))[t], v);
}

// ---------------- finalize layer 1: out1 = relu(dinv*ACC + b1) ----------------
__global__ void k_final1(const float* __restrict__ ACC, const float* __restrict__ dinv,
                         const float* __restrict__ b1, float* __restrict__ out1) {
    int idx = blockIdx.x * blockDim.x + threadIdx.x;
    if (idx >= N_NODES * F1) return;
    int r = idx / F1;
    int c = idx - r * F1;
    out1[idx] = fmaxf(fmaf(dinv[r], ACC[idx], b1[c]), 0.0f);
}

// ---------------- finalize layer 2: Z = dinv*ACC2 + b2 ----------------
__global__ void k_final2(const float* __restrict__ ACC2, const float* __restrict__ dinv,
                         const float* __restrict__ b2, float* __restrict__ Z) {
    int idx = blockIdx.x * blockDim.x + threadIdx.x;
    if (idx >= N_NODES * F2) return;
    int r = idx >> 6;
    int c = idx & 63;
    Z[idx] = fmaf(dinv[r], ACC2[idx], b2[c]);
}

// ---------------- decode: logits[e] = dot(Z[src], Z[dst]) over 64 dims ----------------
__global__ void k_decode(const float* __restrict__ Z, const int* __restrict__ src,
                         const int* __restrict__ dst, float* __restrict__ out, int E) {
    int gid = blockIdx.x * blockDim.x + threadIdx.x;
    int e = gid >> 3;
    if (e >= E) return;
    int t = gid & 7;
    int s = __ldg(&src[e]);
    int d = __ldg(&dst[e]);
    const float4* zs = (const float4*)(Z + (size_t)s * F2);
    const float4* zd = (const float4*)(Z + (size_t)d * F2);
    float sum = 0.0f;
#pragma unroll
    for (int i = t; i < 16; i += 8) {
        float4 a = zs[i];
        float4 b = zd[i];
        sum += a.x * b.x + a.y * b.y + a.z * b.z + a.w * b.w;
    }
#pragma unroll
    for (int off = 4; off; off >>= 1) sum += __shfl_down_sync(0xffffffffu, sum, off, 8);
    if (t == 0) out[e] = sum;
}

// ---------------- launch ----------------
extern "C" void kernel_launch(void* const* d_in, const int* in_sizes, int n_in,
                              void* d_out, int out_size) {
    const float* x  = (const float*)d_in[0];
    const int*   ei = (const int*)d_in[1];
    const float* W1 = (const float*)d_in[2];
    const float* b1 = (const float*)d_in[3];
    const float* W2 = (const float*)d_in[4];
    const float* b2 = (const float*)d_in[5];
    float* logits = (float*)d_out;

    const int E = in_sizes[1] / 2;
    const int M = N_NODES;
    const int* src = ei;
    const int* dst = ei + E;

    float *dinv, *G, *ACC, *out1, *G2, *ACC2;
    cudaGetSymbolAddress((void**)&dinv, g_dinv);
    cudaGetSymbolAddress((void**)&G, g_G);
    cudaGetSymbolAddress((void**)&ACC, g_ACC);
    cudaGetSymbolAddress((void**)&out1, g_out1);
    cudaGetSymbolAddress((void**)&G2, g_G2);
    cudaGetSymbolAddress((void**)&ACC2, g_ACC2);

    // --- degrees -> dinv ---
    k_deg_init<<<(M + 255) / 256, 256>>>(dinv, M);
    k_deg_count<<<(E + 255) / 256, 256>>>(dinv, dst, E);
    k_deg_finish<<<(M + 255) / 256, 256>>>(dinv, M);

    // --- layer 1: G = ACC = dinv ⊙ (x @ W1) ---
    {
        dim3 grid((F1 + 127) / 128, (M + 127) / 128);
        gemm_tf32<128, 128, 32, 32, 64><<<grid, 256>>>(
            x, W1, G, ACC, dinv, M, F1, F0, F0, F1, F1);
    }
    k_scatter628<<<(E * 32 + 255) / 256, 256>>>(G, ACC, src, dst, E);
    k_final1<<<(M * F1 + 255) / 256, 256>>>(ACC, dinv, b1, out1);

    // --- layer 2: G2 = ACC2 = dinv ⊙ (out1 @ W2) ---
    {
        dim3 grid(1, (M + 127) / 128);
        gemm_tf32<128, 64, 32, 32, 32><<<grid, 256>>>(
            out1, W2, G2, ACC2, dinv, M, F2, F1, F1, F2, F2);
    }
    k_scatter64<<<(E * 16 + 255) / 256, 256>>>(G2, ACC2, src, dst, E);
    k_final2<<<(M * F2 + 255) / 256, 256>>>(ACC2, dinv, b2, G2);

    // --- decode ---
    k_decode<<<(E * 8 + 255) / 256, 256>>>(G2, src, dst, logits, E);
}

// round 5
// speedup vs baseline: 3.4551x; 1.4642x over previous
#include <cuda_runtime.h>
#include <cstdint>

#define N_NODES 50000
#define E_MAX   400000
#define F0 600
#define F1 628
#define F2 64

// ---------------- scratch ----------------
__device__ float g_dinv[N_NODES];
__device__ float g_G  [(size_t)N_NODES * F1];
__device__ float g_out1[(size_t)N_NODES * F1];   // also reused as x_tf32 before GEMM1
__device__ float g_G2 [(size_t)N_NODES * F2];
__device__ float g_Z  [(size_t)N_NODES * F2];
__device__ float g_W1r[F0 * F1];
__device__ float g_W2r[F1 * F2];
__device__ int   g_cnt[N_NODES];
__device__ int   g_rowptr[N_NODES + 1];
__device__ int   g_cursor[N_NODES];
__device__ int   g_esrc[E_MAX];

// ---------------- tf32 helper ----------------
__device__ __forceinline__ float to_tf32(float x) {
    uint32_t u;
    asm("cvt.rna.tf32.f32 %0, %1;" : "=r"(u) : "f"(x));
    return __uint_as_float(u);
}
__device__ __forceinline__ void mma_16x8x8(float* d, const float* a, const float* b) {
    asm volatile(
        "mma.sync.aligned.m16n8k8.row.col.f32.tf32.tf32.f32 "
        "{%0,%1,%2,%3}, {%4,%5,%6,%7}, {%8,%9}, {%0,%1,%2,%3};"
        : "+f"(d[0]), "+f"(d[1]), "+f"(d[2]), "+f"(d[3])
        : "r"(__float_as_uint(a[0])), "r"(__float_as_uint(a[1])),
          "r"(__float_as_uint(a[2])), "r"(__float_as_uint(a[3])),
          "r"(__float_as_uint(b[0])), "r"(__float_as_uint(b[1])));
}

// ---------------- CSR build ----------------
__global__ void k_zero_int(int* p, int n) {
    int i = blockIdx.x * blockDim.x + threadIdx.x;
    if (i < n) p[i] = 0;
}
__global__ void k_hist(int* cnt, const int* __restrict__ dst, int e) {
    int i = blockIdx.x * blockDim.x + threadIdx.x;
    if (i < e) atomicAdd(&cnt[dst[i]], 1);
}
__global__ void k_scan(const int* __restrict__ cnt, int* __restrict__ rowptr,
                       int* __restrict__ cursor, int n) {
    __shared__ int part[1024];
    int tid = threadIdx.x;
    int chunk = (n + 1023) / 1024;
    int base = tid * chunk;
    int s = 0;
    for (int i = 0; i < chunk; i++) {
        int idx = base + i;
        if (idx < n) s += cnt[idx];
    }
    part[tid] = s;
    __syncthreads();
    for (int off = 1; off < 1024; off <<= 1) {
        int v = (tid >= off) ? part[tid - off] : 0;
        __syncthreads();
        part[tid] += v;
        __syncthreads();
    }
    int excl = (tid == 0) ? 0 : part[tid - 1];
    for (int i = 0; i < chunk; i++) {
        int idx = base + i;
        if (idx < n) {
            rowptr[idx] = excl;
            cursor[idx] = excl;
            excl += cnt[idx];
        }
    }
    if (tid == 1023) rowptr[n] = part[1023];
}
__global__ void k_dinv(const int* __restrict__ cnt, float* __restrict__ dinv, int n) {
    int i = blockIdx.x * blockDim.x + threadIdx.x;
    if (i < n) dinv[i] = rsqrtf((float)cnt[i] + 1.0f);
}
__global__ void k_fill(int* cursor, int* esrc, const int* __restrict__ src,
                       const int* __restrict__ dst, int e) {
    int i = blockIdx.x * blockDim.x + threadIdx.x;
    if (i >= e) return;
    int pos = atomicAdd(&cursor[dst[i]], 1);
    esrc[pos] = src[i];
}

// ---------------- tf32 pre-round ----------------
__global__ void k_round4(const float4* __restrict__ in, float4* __restrict__ out, int n4) {
    int i = blockIdx.x * blockDim.x + threadIdx.x;
    if (i >= n4) return;
    float4 v = in[i];
    v.x = to_tf32(v.x); v.y = to_tf32(v.y); v.z = to_tf32(v.z); v.w = to_tf32(v.w);
    out[i] = v;
}

// ---------------- double-buffered cp.async tf32 GEMM ----------------
// C = rowScale ⊙ (A@B); A,B pre-rounded to tf32 bits. K%4==0, N%4==0.
// Correctness note: only B needs zero-fill at the K edge (zero B rows kill
// garbage A columns in the MMA sum). A loads clamp addresses and always copy.
// M/N-edge garbage never reaches memory (guarded epilogue stores).
template <int BM, int BN, int BK, int WM, int WN>
__global__ __launch_bounds__((BM / WM) * (BN / WN) * 32, 2)
void gemm_tf32_db(const float* __restrict__ A, const float* __restrict__ B,
                  float* __restrict__ C, const float* __restrict__ rowScale,
                  int M, int N, int K, int lda, int ldb, int ldc) {
    constexpr int WARPS_M = BM / WM;
    constexpr int WARPS_N = BN / WN;
    constexpr int NTHREADS = WARPS_M * WARPS_N * 32;
    constexpr int MT = WM / 16;
    constexpr int NT = WN / 8;
    constexpr int LDA_S = BK + 4;
    constexpr int LDB_S = BN + 8;
    constexpr int LA = (BM * BK / 4) / NTHREADS;
    constexpr int LB = (BK * BN / 4) / NTHREADS;

    __shared__ float As[2][BM][LDA_S];
    __shared__ float Bs[2][BK][LDB_S];

    const int tid = threadIdx.x;
    const int lane = tid & 31;
    const int warp = tid >> 5;
    const int warpM = warp / WARPS_N;
    const int warpN = warp % WARPS_N;
    const int gid = lane >> 2;
    const int tig = lane & 3;
    const int rowBase = blockIdx.y * BM;
    const int colBase = blockIdx.x * BN;

    float acc[MT][NT][4];
#pragma unroll
    for (int i = 0; i < MT; i++)
#pragma unroll
        for (int j = 0; j < NT; j++)
#pragma unroll
            for (int q = 0; q < 4; q++) acc[i][j][q] = 0.0f;

    auto loadTiles = [&](int buf, int k0) {
#pragma unroll
        for (int i = 0; i < LA; i++) {
            int f = tid + i * NTHREADS;
            int row = f / (BK / 4);
            int k = (f % (BK / 4)) * 4;
            int grow = min(rowBase + row, M - 1);
            int gk = min(k0 + k, ((K - 4) / 4) * 4);   // clamp, 16B-aligned, in-bounds
            const float* gp = A + (size_t)grow * lda + gk;
            uint32_t sa = (uint32_t)__cvta_generic_to_shared(&As[buf][row][k]);
            asm volatile("cp.async.cg.shared.global [%0], [%1], 16;\n"
                         :: "r"(sa), "l"(gp));
        }
#pragma unroll
        for (int i = 0; i < LB; i++) {
            int f = tid + i * NTHREADS;
            int krow = f / (BN / 4);
            int n = (f % (BN / 4)) * 4;
            int gk = k0 + krow;
            int gcol = colBase + n;
            int bytes = (gk < K && gcol < N) ? 16 : 0;   // zfill: B MUST be zero past edges
            const float* gp = B + (size_t)min(gk, K - 1) * ldb + min(gcol, ((N - 4) / 4) * 4);
            uint32_t sa = (uint32_t)__cvta_generic_to_shared(&Bs[buf][krow][n]);
            asm volatile("cp.async.cg.shared.global [%0], [%1], 16, %2;\n"
                         :: "r"(sa), "l"(gp), "r"(bytes));
        }
    };

    const int nIter = (K + BK - 1) / BK;
    loadTiles(0, 0);
    asm volatile("cp.async.commit_group;\n" ::: "memory");

    for (int it = 0; it < nIter; it++) {
        if (it + 1 < nIter) {
            loadTiles((it + 1) & 1, (it + 1) * BK);
            asm volatile("cp.async.commit_group;\n" ::: "memory");
            asm volatile("cp.async.wait_group 1;\n" ::: "memory");
        } else {
            asm volatile("cp.async.wait_group 0;\n" ::: "memory");
        }
        __syncthreads();

        const int buf = it & 1;
#pragma unroll
        for (int kk = 0; kk < BK / 8; kk++) {
            const int kb = kk * 8;
            float a[MT][4];
            float b[NT][2];
#pragma unroll
            for (int mt = 0; mt < MT; mt++) {
                int r = warpM * WM + mt * 16 + gid;
                a[mt][0] = As[buf][r][kb + tig];
                a[mt][1] = As[buf][r + 8][kb + tig];
                a[mt][2] = As[buf][r][kb + tig + 4];
                a[mt][3] = As[buf][r + 8][kb + tig + 4];
            }
#pragma unroll
            for (int nt = 0; nt < NT; nt++) {
                int c = warpN * WN + nt * 8 + gid;
                b[nt][0] = Bs[buf][kb + tig][c];
                b[nt][1] = Bs[buf][kb + tig + 4][c];
            }
#pragma unroll
            for (int mt = 0; mt < MT; mt++)
#pragma unroll
                for (int nt = 0; nt < NT; nt++)
                    mma_16x8x8(acc[mt][nt], a[mt], b[nt]);
        }
        __syncthreads();
    }

#pragma unroll
    for (int mt = 0; mt < MT; mt++) {
        int r0 = rowBase + warpM * WM + mt * 16 + gid;
        int r1 = r0 + 8;
        float s0 = (r0 < M) ? __ldg(&rowScale[r0]) : 0.0f;
        float s1 = (r1 < M) ? __ldg(&rowScale[r1]) : 0.0f;
#pragma unroll
        for (int nt = 0; nt < NT; nt++) {
            int c0 = colBase + warpN * WN + nt * 8 + 2 * tig;
            if (c0 >= N) continue;
            if (r0 < M)
                *(float2*)(C + (size_t)r0 * ldc + c0) =
                    make_float2(s0 * acc[mt][nt][0], s0 * acc[mt][nt][1]);
            if (r1 < M)
                *(float2*)(C + (size_t)r1 * ldc + c0) =
                    make_float2(s1 * acc[mt][nt][2], s1 * acc[mt][nt][3]);
        }
    }
}

// ---------------- fused aggregation layer 1 (gather) ----------------
// out1[d] = tf32( relu( dinv[d] * (G[d] + Σ_{s∈in(d)} G[s]) + b1 ) )
__global__ void k_agg1(const float4* __restrict__ G4, const int* __restrict__ rowptr,
                       const int* __restrict__ esrc, const float* __restrict__ dinv,
                       const float4* __restrict__ b1_4, float4* __restrict__ out1_4) {
    const int d = blockIdx.x;
    const int t = threadIdx.x;
    if (t >= F1 / 4) return;
    const int j0 = rowptr[d], j1 = rowptr[d + 1];
    float4 acc = G4[(size_t)d * (F1 / 4) + t];
    for (int j = j0; j < j1; j++) {
        int s = __ldg(&esrc[j]);
        float4 v = G4[(size_t)s * (F1 / 4) + t];
        acc.x += v.x; acc.y += v.y; acc.z += v.z; acc.w += v.w;
    }
    float di = dinv[d];
    float4 b = b1_4[t];
    float4 r;
    r.x = to_tf32(fmaxf(fmaf(di, acc.x, b.x), 0.0f));
    r.y = to_tf32(fmaxf(fmaf(di, acc.y, b.y), 0.0f));
    r.z = to_tf32(fmaxf(fmaf(di, acc.z, b.z), 0.0f));
    r.w = to_tf32(fmaxf(fmaf(di, acc.w, b.w), 0.0f));
    out1_4[(size_t)d * (F1 / 4) + t] = r;
}

// ---------------- fused aggregation layer 2 (gather, warp/node) ----------------
__global__ void k_agg2(const float2* __restrict__ G2_2, const int* __restrict__ rowptr,
                       const int* __restrict__ esrc, const float* __restrict__ dinv,
                       const float2* __restrict__ b2_2, float2* __restrict__ Z2) {
    int gw = (blockIdx.x * blockDim.x + threadIdx.x) >> 5;
    if (gw >= N_NODES) return;
    int lane = threadIdx.x & 31;
    const int j0 = rowptr[gw], j1 = rowptr[gw + 1];
    float2 acc = G2_2[(size_t)gw * 32 + lane];
    for (int j = j0; j < j1; j++) {
        int s = __ldg(&esrc[j]);
        float2 v = G2_2[(size_t)s * 32 + lane];
        acc.x += v.x; acc.y += v.y;
    }
    float di = dinv[gw];
    float2 b = b2_2[lane];
    Z2[(size_t)gw * 32 + lane] = make_float2(fmaf(di, acc.x, b.x), fmaf(di, acc.y, b.y));
}

// ---------------- decode: logits[e] = dot(Z[src], Z[dst]) ----------------
__global__ void k_decode(const float* __restrict__ Z, const int* __restrict__ src,
                         const int* __restrict__ dst, float* __restrict__ out, int E) {
    int gid = blockIdx.x * blockDim.x + threadIdx.x;
    int e = gid >> 3;
    if (e >= E) return;
    int t = gid & 7;
    int s = __ldg(&src[e]);
    int d = __ldg(&dst[e]);
    const float4* zs = (const float4*)(Z + (size_t)s * F2);
    const float4* zd = (const float4*)(Z + (size_t)d * F2);
    float sum = 0.0f;
#pragma unroll
    for (int i = t; i < 16; i += 8) {
        float4 a = zs[i];
        float4 b = zd[i];
        sum += a.x * b.x + a.y * b.y + a.z * b.z + a.w * b.w;
    }
#pragma unroll
    for (int off = 4; off; off >>= 1) sum += __shfl_down_sync(0xffffffffu, sum, off, 8);
    if (t == 0) out[e] = sum;
}

// ---------------- launch ----------------
extern "C" void kernel_launch(void* const* d_in, const int* in_sizes, int n_in,
                              void* d_out, int out_size) {
    const float* x  = (const float*)d_in[0];
    const int*   ei = (const int*)d_in[1];
    const float* W1 = (const float*)d_in[2];
    const float* b1 = (const float*)d_in[3];
    const float* W2 = (const float*)d_in[4];
    const float* b2 = (const float*)d_in[5];
    float* logits = (float*)d_out;

    const int E = in_sizes[1] / 2;
    const int M = N_NODES;
    const int* src = ei;
    const int* dst = ei + E;

    float *dinv, *G, *out1, *G2, *Z, *W1r, *W2r;
    int *cnt, *rowptr, *cursor, *esrc;
    cudaGetSymbolAddress((void**)&dinv, g_dinv);
    cudaGetSymbolAddress((void**)&G, g_G);
    cudaGetSymbolAddress((void**)&out1, g_out1);
    cudaGetSymbolAddress((void**)&G2, g_G2);
    cudaGetSymbolAddress((void**)&Z, g_Z);
    cudaGetSymbolAddress((void**)&W1r, g_W1r);
    cudaGetSymbolAddress((void**)&W2r, g_W2r);
    cudaGetSymbolAddress((void**)&cnt, g_cnt);
    cudaGetSymbolAddress((void**)&rowptr, g_rowptr);
    cudaGetSymbolAddress((void**)&cursor, g_cursor);
    cudaGetSymbolAddress((void**)&esrc, g_esrc);

    // --- CSR build + dinv ---
    k_zero_int<<<(M + 255) / 256, 256>>>(cnt, M);
    k_hist<<<(E + 255) / 256, 256>>>(cnt, dst, E);
    k_scan<<<1, 1024>>>(cnt, rowptr, cursor, M);
    k_dinv<<<(M + 255) / 256, 256>>>(cnt, dinv, M);
    k_fill<<<(E + 255) / 256, 256>>>(cursor, esrc, src, dst, E);

    // --- pre-round inputs to tf32 (x into out1 buffer, reused) ---
    float* xr = out1;  // N*F0 <= N*F1, free until k_agg1 writes out1
    k_round4<<<((M * F0 / 4) + 255) / 256, 256>>>((const float4*)x, (float4*)xr, M * F0 / 4);
    k_round4<<<((F0 * F1 / 4) + 255) / 256, 256>>>((const float4*)W1, (float4*)W1r, F0 * F1 / 4);
    k_round4<<<((F1 * F2 / 4) + 255) / 256, 256>>>((const float4*)W2, (float4*)W2r, F1 * F2 / 4);

    // --- layer 1: G = dinv ⊙ (x @ W1) ---
    {
        dim3 grid((F1 + 127) / 128, (M + 127) / 128);
        gemm_tf32_db<128, 128, 16, 32, 64><<<grid, 256>>>(
            xr, W1r, G, dinv, M, F1, F0, F0, F1, F1);
    }
    // fused gather-aggregate + relu + bias + tf32 round
    k_agg1<<<M, 160>>>((const float4*)G, rowptr, esrc, dinv,
                       (const float4*)b1, (float4*)out1);

    // --- layer 2: G2 = dinv ⊙ (out1 @ W2) ---
    {
        dim3 grid(1, (M + 127) / 128);
        gemm_tf32_db<128, 64, 16, 32, 32><<<grid, 256>>>(
            out1, W2r, G2, dinv, M, F2, F1, F1, F2, F2);
    }
    k_agg2<<<(M * 32 + 255) / 256, 256>>>((const float2*)G2, rowptr, esrc, dinv,
                                          (const float2*)b2, (float2*)Z);

    // --- decode ---
    k_decode<<<(E * 8 + 255) / 256, 256>>>(Z, src, dst, logits, E);
}

// round 8
// speedup vs baseline: 3.5997x; 1.0419x over previous
#include <cuda_runtime.h>
#include <cstdint>

#define N_NODES 50000
#define E_MAX   400000
#define F0 600
#define F1 628
#define F2 64

// ---------------- scratch ----------------
__device__ float g_dinv[N_NODES];
__device__ float g_G  [(size_t)N_NODES * F1];
__device__ float g_out1[(size_t)N_NODES * F1];   // reused as x_tf32 before agg1
__device__ float g_G2 [(size_t)N_NODES * F2];
__device__ float g_Z  [(size_t)N_NODES * F2];
__device__ float g_W1r[F0 * F1];
__device__ float g_W2r[F1 * F2];
__device__ int   g_cnt[N_NODES];
__device__ int   g_rowptr[N_NODES + 1];
__device__ int   g_cursor[N_NODES];
__device__ int   g_esrc[E_MAX];

// ---------------- tf32 helpers ----------------
// RNA rounding is REQUIRED: raw-f32 truncation has a correlated bias that
// accumulates linearly over K and fails the 1e-3 gate (measured 2.9e-3).
__device__ __forceinline__ float to_tf32(float x) {
    uint32_t u;
    asm("cvt.rna.tf32.f32 %0, %1;" : "=r"(u) : "f"(x));
    return __uint_as_float(u);
}
__device__ __forceinline__ void mma_16x8x8(float* d, const float* a, const float* b) {
    asm volatile(
        "mma.sync.aligned.m16n8k8.row.col.f32.tf32.tf32.f32 "
        "{%0,%1,%2,%3}, {%4,%5,%6,%7}, {%8,%9}, {%0,%1,%2,%3};"
        : "+f"(d[0]), "+f"(d[1]), "+f"(d[2]), "+f"(d[3])
        : "r"(__float_as_uint(a[0])), "r"(__float_as_uint(a[1])),
          "r"(__float_as_uint(a[2])), "r"(__float_as_uint(a[3])),
          "r"(__float_as_uint(b[0])), "r"(__float_as_uint(b[1])));
}

// ---------------- CSR build ----------------
__global__ void k_zero_int(int* p, int n) {
    int i = blockIdx.x * blockDim.x + threadIdx.x;
    if (i < n) p[i] = 0;
}
__global__ void k_hist(int* cnt, const int* __restrict__ dst, int e) {
    int i = blockIdx.x * blockDim.x + threadIdx.x;
    if (i < e) atomicAdd(&cnt[dst[i]], 1);
}
__global__ void k_scan(const int* __restrict__ cnt, int* __restrict__ rowptr,
                       int* __restrict__ cursor, int n) {
    __shared__ int part[1024];
    int tid = threadIdx.x;
    int chunk = (n + 1023) / 1024;
    int base = tid * chunk;
    int s = 0;
    for (int i = 0; i < chunk; i++) {
        int idx = base + i;
        if (idx < n) s += cnt[idx];
    }
    part[tid] = s;
    __syncthreads();
    for (int off = 1; off < 1024; off <<= 1) {
        int v = (tid >= off) ? part[tid - off] : 0;
        __syncthreads();
        part[tid] += v;
        __syncthreads();
    }
    int excl = (tid == 0) ? 0 : part[tid - 1];
    for (int i = 0; i < chunk; i++) {
        int idx = base + i;
        if (idx < n) {
            rowptr[idx] = excl;
            cursor[idx] = excl;
            excl += cnt[idx];
        }
    }
    if (tid == 1023) rowptr[n] = part[1023];
}
__global__ void k_dinv(const int* __restrict__ cnt, float* __restrict__ dinv, int n) {
    int i = blockIdx.x * blockDim.x + threadIdx.x;
    if (i < n) dinv[i] = rsqrtf((float)cnt[i] + 1.0f);
}
__global__ void k_fill(int* cursor, int* esrc, const int* __restrict__ src,
                       const int* __restrict__ dst, int e) {
    int i = blockIdx.x * blockDim.x + threadIdx.x;
    if (i >= e) return;
    int pos = atomicAdd(&cursor[dst[i]], 1);
    esrc[pos] = src[i];
}

// ---------------- tf32 pre-round ----------------
__global__ void k_round4(const float4* __restrict__ in, float4* __restrict__ out, int n4) {
    int i = blockIdx.x * blockDim.x + threadIdx.x;
    if (i >= n4) return;
    float4 v = in[i];
    v.x = to_tf32(v.x); v.y = to_tf32(v.y); v.z = to_tf32(v.z); v.w = to_tf32(v.w);
    out[i] = v;
}

// ---------------- double-buffered cp.async tf32 GEMM (dynamic smem) ----------------
// C = rowScale ⊙ (A@B); A,B pre-rounded to tf32 bits. Only B needs zero-fill
// at K/N edges; A loads clamp addresses. Guarded epilogue stores.
template <int BM, int BN, int BK, int WM, int WN>
__global__ __launch_bounds__((BM / WM) * (BN / WN) * 32, 2)
void gemm_tf32_db(const float* __restrict__ A, const float* __restrict__ B,
                  float* __restrict__ C, const float* __restrict__ rowScale,
                  int M, int N, int K, int lda, int ldb, int ldc) {
    constexpr int WARPS_M = BM / WM;
    constexpr int WARPS_N = BN / WN;
    constexpr int NTHREADS = WARPS_M * WARPS_N * 32;
    constexpr int MT = WM / 16;
    constexpr int NT = WN / 8;
    constexpr int LDA_S = BK + 4;
    constexpr int LDB_S = BN + 8;
    constexpr int LA = (BM * BK / 4) / NTHREADS;
    constexpr int LB = (BK * BN / 4) / NTHREADS;

    extern __shared__ float sm[];
    float* As = sm;                       // [2][BM][LDA_S]
    float* Bs = sm + 2 * BM * LDA_S;      // [2][BK][LDB_S]

    const int tid = threadIdx.x;
    const int lane = tid & 31;
    const int warp = tid >> 5;
    const int warpM = warp / WARPS_N;
    const int warpN = warp % WARPS_N;
    const int gid = lane >> 2;
    const int tig = lane & 3;
    const int rowBase = blockIdx.y * BM;
    const int colBase = blockIdx.x * BN;

    float acc[MT][NT][4];
#pragma unroll
    for (int i = 0; i < MT; i++)
#pragma unroll
        for (int j = 0; j < NT; j++)
#pragma unroll
            for (int q = 0; q < 4; q++) acc[i][j][q] = 0.0f;

    auto loadTiles = [&](int buf, int k0) {
#pragma unroll
        for (int i = 0; i < LA; i++) {
            int f = tid + i * NTHREADS;
            int row = f / (BK / 4);
            int k = (f % (BK / 4)) * 4;
            int grow = min(rowBase + row, M - 1);
            int gk = min(k0 + k, ((K - 4) / 4) * 4);
            const float* gp = A + (size_t)grow * lda + gk;
            uint32_t sa = (uint32_t)__cvta_generic_to_shared(
                &As[(size_t)buf * BM * LDA_S + row * LDA_S + k]);
            asm volatile("cp.async.cg.shared.global [%0], [%1], 16;\n"
                         :: "r"(sa), "l"(gp));
        }
#pragma unroll
        for (int i = 0; i < LB; i++) {
            int f = tid + i * NTHREADS;
            int krow = f / (BN / 4);
            int n = (f % (BN / 4)) * 4;
            int gk = k0 + krow;
            int gcol = colBase + n;
            int bytes = (gk < K && gcol < N) ? 16 : 0;
            const float* gp = B + (size_t)min(gk, K - 1) * ldb + min(gcol, ((N - 4) / 4) * 4);
            uint32_t sa = (uint32_t)__cvta_generic_to_shared(
                &Bs[(size_t)buf * BK * LDB_S + krow * LDB_S + n]);
            asm volatile("cp.async.cg.shared.global [%0], [%1], 16, %2;\n"
                         :: "r"(sa), "l"(gp), "r"(bytes));
        }
    };

    const int nIter = (K + BK - 1) / BK;
    loadTiles(0, 0);
    asm volatile("cp.async.commit_group;\n" ::: "memory");

    for (int it = 0; it < nIter; it++) {
        if (it + 1 < nIter) {
            loadTiles((it + 1) & 1, (it + 1) * BK);
            asm volatile("cp.async.commit_group;\n" ::: "memory");
            asm volatile("cp.async.wait_group 1;\n" ::: "memory");
        } else {
            asm volatile("cp.async.wait_group 0;\n" ::: "memory");
        }
        __syncthreads();

        const int buf = it & 1;
        const float* Ab = As + (size_t)buf * BM * LDA_S;
        const float* Bb = Bs + (size_t)buf * BK * LDB_S;
#pragma unroll
        for (int kk = 0; kk < BK / 8; kk++) {
            const int kb = kk * 8;
            float a[MT][4];
            float b[NT][2];
#pragma unroll
            for (int mt = 0; mt < MT; mt++) {
                int r = warpM * WM + mt * 16 + gid;
                a[mt][0] = Ab[r * LDA_S + kb + tig];
                a[mt][1] = Ab[(r + 8) * LDA_S + kb + tig];
                a[mt][2] = Ab[r * LDA_S + kb + tig + 4];
                a[mt][3] = Ab[(r + 8) * LDA_S + kb + tig + 4];
            }
#pragma unroll
            for (int nt = 0; nt < NT; nt++) {
                int c = warpN * WN + nt * 8 + gid;
                b[nt][0] = Bb[(kb + tig) * LDB_S + c];
                b[nt][1] = Bb[(kb + tig + 4) * LDB_S + c];
            }
#pragma unroll
            for (int mt = 0; mt < MT; mt++)
#pragma unroll
                for (int nt = 0; nt < NT; nt++)
                    mma_16x8x8(acc[mt][nt], a[mt], b[nt]);
        }
        __syncthreads();
    }

#pragma unroll
    for (int mt = 0; mt < MT; mt++) {
        int r0 = rowBase + warpM * WM + mt * 16 + gid;
        int r1 = r0 + 8;
        float s0 = (r0 < M) ? __ldg(&rowScale[r0]) : 0.0f;
        float s1 = (r1 < M) ? __ldg(&rowScale[r1]) : 0.0f;
#pragma unroll
        for (int nt = 0; nt < NT; nt++) {
            int c0 = colBase + warpN * WN + nt * 8 + 2 * tig;
            if (c0 >= N) continue;
            if (r0 < M)
                *(float2*)(C + (size_t)r0 * ldc + c0) =
                    make_float2(s0 * acc[mt][nt][0], s0 * acc[mt][nt][1]);
            if (r1 < M)
                *(float2*)(C + (size_t)r1 * ldc + c0) =
                    make_float2(s1 * acc[mt][nt][2], s1 * acc[mt][nt][3]);
        }
    }
}

// ---------------- fused aggregation layer 1 (gather) ----------------
// out1[d] = tf32( relu( dinv[d] * (G[d] + Σ_{s∈in(d)} G[s]) + b1 ) )
__global__ void k_agg1(const float4* __restrict__ G4, const int* __restrict__ rowptr,
                       const int* __restrict__ esrc, const float* __restrict__ dinv,
                       const float4* __restrict__ b1_4, float4* __restrict__ out1_4) {
    const int d = blockIdx.x;
    const int t = threadIdx.x;
    if (t >= F1 / 4) return;
    const int j0 = rowptr[d], j1 = rowptr[d + 1];
    float4 acc = G4[(size_t)d * (F1 / 4) + t];
    for (int j = j0; j < j1; j++) {
        int s = __ldg(&esrc[j]);
        float4 v = G4[(size_t)s * (F1 / 4) + t];
        acc.x += v.x; acc.y += v.y; acc.z += v.z; acc.w += v.w;
    }
    float di = dinv[d];
    float4 b = b1_4[t];
    float4 r;
    r.x = to_tf32(fmaxf(fmaf(di, acc.x, b.x), 0.0f));
    r.y = to_tf32(fmaxf(fmaf(di, acc.y, b.y), 0.0f));
    r.z = to_tf32(fmaxf(fmaf(di, acc.z, b.z), 0.0f));
    r.w = to_tf32(fmaxf(fmaf(di, acc.w, b.w), 0.0f));
    out1_4[(size_t)d * (F1 / 4) + t] = r;
}

// ---------------- fused aggregation layer 2 ----------------
__global__ void k_agg2(const float2* __restrict__ G2_2, const int* __restrict__ rowptr,
                       const int* __restrict__ esrc, const float* __restrict__ dinv,
                       const float2* __restrict__ b2_2, float2* __restrict__ Z2) {
    int gw = (blockIdx.x * blockDim.x + threadIdx.x) >> 5;
    if (gw >= N_NODES) return;
    int lane = threadIdx.x & 31;
    const int j0 = rowptr[gw], j1 = rowptr[gw + 1];
    float2 acc = G2_2[(size_t)gw * 32 + lane];
    for (int j = j0; j < j1; j++) {
        int s = __ldg(&esrc[j]);
        float2 v = G2_2[(size_t)s * 32 + lane];
        acc.x += v.x; acc.y += v.y;
    }
    float di = dinv[gw];
    float2 b = b2_2[lane];
    Z2[(size_t)gw * 32 + lane] = make_float2(fmaf(di, acc.x, b.x), fmaf(di, acc.y, b.y));
}

// ---------------- decode ----------------
__global__ void k_decode(const float* __restrict__ Z, const int* __restrict__ src,
                         const int* __restrict__ dst, float* __restrict__ out, int E) {
    int gid = blockIdx.x * blockDim.x + threadIdx.x;
    int e = gid >> 3;
    if (e >= E) return;
    int t = gid & 7;
    int s = __ldg(&src[e]);
    int d = __ldg(&dst[e]);
    const float4* zs = (const float4*)(Z + (size_t)s * F2);
    const float4* zd = (const float4*)(Z + (size_t)d * F2);
    float sum = 0.0f;
#pragma unroll
    for (int i = t; i < 16; i += 8) {
        float4 a = zs[i];
        float4 b = zd[i];
        sum += a.x * b.x + a.y * b.y + a.z * b.z + a.w * b.w;
    }
#pragma unroll
    for (int off = 4; off; off >>= 1) sum += __shfl_down_sync(0xffffffffu, sum, off, 8);
    if (t == 0) out[e] = sum;
}

// ---------------- launch ----------------
extern "C" void kernel_launch(void* const* d_in, const int* in_sizes, int n_in,
                              void* d_out, int out_size) {
    const float* x  = (const float*)d_in[0];
    const int*   ei = (const int*)d_in[1];
    const float* W1 = (const float*)d_in[2];
    const float* b1 = (const float*)d_in[3];
    const float* W2 = (const float*)d_in[4];
    const float* b2 = (const float*)d_in[5];
    float* logits = (float*)d_out;

    const int E = in_sizes[1] / 2;
    const int M = N_NODES;
    const int* src = ei;
    const int* dst = ei + E;

    float *dinv, *G, *out1, *G2, *Z, *W1r, *W2r;
    int *cnt, *rowptr, *cursor, *esrc;
    cudaGetSymbolAddress((void**)&dinv, g_dinv);
    cudaGetSymbolAddress((void**)&G, g_G);
    cudaGetSymbolAddress((void**)&out1, g_out1);
    cudaGetSymbolAddress((void**)&G2, g_G2);
    cudaGetSymbolAddress((void**)&Z, g_Z);
    cudaGetSymbolAddress((void**)&W1r, g_W1r);
    cudaGetSymbolAddress((void**)&W2r, g_W2r);
    cudaGetSymbolAddress((void**)&cnt, g_cnt);
    cudaGetSymbolAddress((void**)&rowptr, g_rowptr);
    cudaGetSymbolAddress((void**)&cursor, g_cursor);
    cudaGetSymbolAddress((void**)&esrc, g_esrc);

    // --- CSR build + dinv ---
    k_zero_int<<<(M + 255) / 256, 256>>>(cnt, M);
    k_hist<<<(E + 255) / 256, 256>>>(cnt, dst, E);
    k_scan<<<1, 1024>>>(cnt, rowptr, cursor, M);
    k_dinv<<<(M + 255) / 256, 256>>>(cnt, dinv, M);
    k_fill<<<(E + 255) / 256, 256>>>(cursor, esrc, src, dst, E);

    // --- pre-round inputs to tf32 (x into out1 buffer, reused) ---
    float* xr = out1;  // N*F0 <= N*F1, free until k_agg1 writes out1
    k_round4<<<((M * F0 / 4) + 255) / 256, 256>>>((const float4*)x, (float4*)xr, M * F0 / 4);
    k_round4<<<((F0 * F1 / 4) + 255) / 256, 256>>>((const float4*)W1, (float4*)W1r, F0 * F1 / 4);
    k_round4<<<((F1 * F2 / 4) + 255) / 256, 256>>>((const float4*)W2, (float4*)W2r, F1 * F2 / 4);

    // --- layer 1: G = dinv ⊙ (x @ W1), BK=32 ---
    {
        constexpr int SM1 = (2 * 128 * 36 + 2 * 32 * 136) * 4;  // 71680 B
        cudaFuncSetAttribute((const void*)gemm_tf32_db<128, 128, 32, 32, 64>,
                             cudaFuncAttributeMaxDynamicSharedMemorySize, SM1);
        dim3 grid((F1 + 127) / 128, (M + 127) / 128);
        gemm_tf32_db<128, 128, 32, 32, 64><<<grid, 256, SM1>>>(
            xr, W1r, G, dinv, M, F1, F0, F0, F1, F1);
    }
    k_agg1<<<M, 160>>>((const float4*)G, rowptr, esrc, dinv,
                       (const float4*)b1, (float4*)out1);

    // --- layer 2: G2 = dinv ⊙ (out1 @ W2) ---
    {
        constexpr int SM2 = (2 * 128 * 20 + 2 * 16 * 72) * 4;   // 29696 B
        dim3 grid(1, (M + 127) / 128);
        gemm_tf32_db<128, 64, 16, 32, 32><<<grid, 256, SM2>>>(
            out1, W2r, G2, dinv, M, F2, F1, F1, F2, F2);
    }
    k_agg2<<<(M * 32 + 255) / 256, 256>>>((const float2*)G2, rowptr, esrc, dinv,
                                          (const float2*)b2, (float2*)Z);

    // --- decode ---
    k_decode<<<(E * 8 + 255) / 256, 256>>>(Z, src, dst, logits, E);
}

// round 11
// speedup vs baseline: 3.9924x; 1.1091x over previous
#include <cuda_runtime.h>
#include <cstdint>

#define N_NODES 50000
#define E_MAX   400000
#define F0 600
#define F1 628
#define F2 64

// ---------------- scratch ----------------
__device__ float g_dinv[N_NODES];
__device__ float g_Y  [(size_t)N_NODES * F0];    // aggregated x (tf32-rounded)
__device__ float g_out1[(size_t)N_NODES * F1];
__device__ float g_G2 [(size_t)N_NODES * F2];
__device__ float g_Z  [(size_t)N_NODES * F2];
__device__ float g_W1r[F0 * F1];
__device__ float g_W2r[F1 * F2];
__device__ int   g_cnt[N_NODES];
__device__ int   g_rowptr[N_NODES + 1];
__device__ int   g_cursor[N_NODES];
__device__ int   g_esrc[E_MAX];

// ---------------- tf32 helpers ----------------
// RNA rounding is REQUIRED: raw-f32 truncation into mma.tf32 has a correlated
// bias that accumulates linearly over K and fails the 1e-3 gate (measured 2.9e-3).
__device__ __forceinline__ float to_tf32(float x) {
    uint32_t u;
    asm("cvt.rna.tf32.f32 %0, %1;" : "=r"(u) : "f"(x));
    return __uint_as_float(u);
}
__device__ __forceinline__ void mma_16x8x8(float* d, const float* a, const float* b) {
    asm volatile(
        "mma.sync.aligned.m16n8k8.row.col.f32.tf32.tf32.f32 "
        "{%0,%1,%2,%3}, {%4,%5,%6,%7}, {%8,%9}, {%0,%1,%2,%3};"
        : "+f"(d[0]), "+f"(d[1]), "+f"(d[2]), "+f"(d[3])
        : "r"(__float_as_uint(a[0])), "r"(__float_as_uint(a[1])),
          "r"(__float_as_uint(a[2])), "r"(__float_as_uint(a[3])),
          "r"(__float_as_uint(b[0])), "r"(__float_as_uint(b[1])));
}

// ---------------- CSR build ----------------
__global__ void k_zero_int(int* p, int n) {
    int i = blockIdx.x * blockDim.x + threadIdx.x;
    if (i < n) p[i] = 0;
}
__global__ void k_hist(int* cnt, const int* __restrict__ dst, int e) {
    int i = blockIdx.x * blockDim.x + threadIdx.x;
    if (i < e) atomicAdd(&cnt[dst[i]], 1);
}
__global__ void k_scan(const int* __restrict__ cnt, int* __restrict__ rowptr,
                       int* __restrict__ cursor, int n) {
    __shared__ int part[1024];
    int tid = threadIdx.x;
    int chunk = (n + 1023) / 1024;
    int base = tid * chunk;
    int s = 0;
    for (int i = 0; i < chunk; i++) {
        int idx = base + i;
        if (idx < n) s += cnt[idx];
    }
    part[tid] = s;
    __syncthreads();
    for (int off = 1; off < 1024; off <<= 1) {
        int v = (tid >= off) ? part[tid - off] : 0;
        __syncthreads();
        part[tid] += v;
        __syncthreads();
    }
    int excl = (tid == 0) ? 0 : part[tid - 1];
    for (int i = 0; i < chunk; i++) {
        int idx = base + i;
        if (idx < n) {
            rowptr[idx] = excl;
            cursor[idx] = excl;
            excl += cnt[idx];
        }
    }
    if (tid == 1023) rowptr[n] = part[1023];
}
__global__ void k_dinv(const int* __restrict__ cnt, float* __restrict__ dinv, int n) {
    int i = blockIdx.x * blockDim.x + threadIdx.x;
    if (i < n) dinv[i] = rsqrtf((float)cnt[i] + 1.0f);
}
__global__ void k_fill(int* cursor, int* esrc, const int* __restrict__ src,
                       const int* __restrict__ dst, int e) {
    int i = blockIdx.x * blockDim.x + threadIdx.x;
    if (i >= e) return;
    int pos = atomicAdd(&cursor[dst[i]], 1);
    esrc[pos] = src[i];
}

// ---------------- tf32 pre-round (weights only) ----------------
__global__ void k_round4(const float4* __restrict__ in, float4* __restrict__ out, int n4) {
    int i = blockIdx.x * blockDim.x + threadIdx.x;
    if (i >= n4) return;
    float4 v = in[i];
    v.x = to_tf32(v.x); v.y = to_tf32(v.y); v.z = to_tf32(v.z); v.w = to_tf32(v.w);
    out[i] = v;
}

// ---------------- aggregate x (600-dim), column-split for L2 residency ----------------
// Y[d] = tf32( dinv[d] * ( Σ_{s∈in(d)} dinv[s]*x[s] + dinv[d]*x[d] ) )
// Called twice with c0/nc covering [0,75) and [75,150) float4 columns.
__global__ void k_aggx(const float4* __restrict__ X4, const int* __restrict__ rowptr,
                       const int* __restrict__ esrc, const float* __restrict__ dinv,
                       float4* __restrict__ Y4, int c0, int nc) {
    const int d = blockIdx.x;
    const int t = threadIdx.x;
    if (t >= nc) return;
    const int col = c0 + t;
    const int j0 = rowptr[d], j1 = rowptr[d + 1];
    const float did = dinv[d];
    float4 xv = X4[(size_t)d * (F0 / 4) + col];
    float4 acc;
    acc.x = did * xv.x; acc.y = did * xv.y; acc.z = did * xv.z; acc.w = did * xv.w;
    for (int j = j0; j < j1; j++) {
        int s = __ldg(&esrc[j]);
        float ds = __ldg(&dinv[s]);
        float4 v = X4[(size_t)s * (F0 / 4) + col];
        acc.x = fmaf(ds, v.x, acc.x);
        acc.y = fmaf(ds, v.y, acc.y);
        acc.z = fmaf(ds, v.z, acc.z);
        acc.w = fmaf(ds, v.w, acc.w);
    }
    float4 r;
    r.x = to_tf32(did * acc.x);
    r.y = to_tf32(did * acc.y);
    r.z = to_tf32(did * acc.z);
    r.w = to_tf32(did * acc.w);
    Y4[(size_t)d * (F0 / 4) + col] = r;
}

// ---------------- double-buffered cp.async tf32 GEMM (dynamic smem) ----------------
// EPI=0: C = rowScale ⊙ (A@B)           (scaleOrBias = per-row dinv)
// EPI=1: C = tf32(relu(A@B + bias))     (scaleOrBias = per-col bias)
template <int BM, int BN, int BK, int WM, int WN, int EPI>
__global__ __launch_bounds__((BM / WM) * (BN / WN) * 32, 2)
void gemm_tf32_db(const float* __restrict__ A, const float* __restrict__ B,
                  float* __restrict__ C, const float* __restrict__ scaleOrBias,
                  int M, int N, int K, int lda, int ldb, int ldc) {
    constexpr int WARPS_M = BM / WM;
    constexpr int WARPS_N = BN / WN;
    constexpr int NTHREADS = WARPS_M * WARPS_N * 32;
    constexpr int MT = WM / 16;
    constexpr int NT = WN / 8;
    constexpr int LDA_S = BK + 4;
    constexpr int LDB_S = BN + 8;
    constexpr int LA = (BM * BK / 4) / NTHREADS;
    constexpr int LB = (BK * BN / 4) / NTHREADS;

    extern __shared__ float sm[];
    float* As = sm;                       // [2][BM][LDA_S]
    float* Bs = sm + 2 * BM * LDA_S;      // [2][BK][LDB_S]

    const int tid = threadIdx.x;
    const int lane = tid & 31;
    const int warp = tid >> 5;
    const int warpM = warp / WARPS_N;
    const int warpN = warp % WARPS_N;
    const int gid = lane >> 2;
    const int tig = lane & 3;
    const int rowBase = blockIdx.y * BM;
    const int colBase = blockIdx.x * BN;

    float acc[MT][NT][4];
#pragma unroll
    for (int i = 0; i < MT; i++)
#pragma unroll
        for (int j = 0; j < NT; j++)
#pragma unroll
            for (int q = 0; q < 4; q++) acc[i][j][q] = 0.0f;

    auto loadTiles = [&](int buf, int k0) {
#pragma unroll
        for (int i = 0; i < LA; i++) {
            int f = tid + i * NTHREADS;
            int row = f / (BK / 4);
            int k = (f % (BK / 4)) * 4;
            int grow = min(rowBase + row, M - 1);
            int gk = min(k0 + k, ((K - 4) / 4) * 4);
            const float* gp = A + (size_t)grow * lda + gk;
            uint32_t sa = (uint32_t)__cvta_generic_to_shared(
                &As[(size_t)buf * BM * LDA_S + row * LDA_S + k]);
            asm volatile("cp.async.cg.shared.global [%0], [%1], 16;\n"
                         :: "r"(sa), "l"(gp));
        }
#pragma unroll
        for (int i = 0; i < LB; i++) {
            int f = tid + i * NTHREADS;
            int krow = f / (BN / 4);
            int n = (f % (BN / 4)) * 4;
            int gk = k0 + krow;
            int gcol = colBase + n;
            int bytes = (gk < K && gcol < N) ? 16 : 0;
            const float* gp = B + (size_t)min(gk, K - 1) * ldb + min(gcol, ((N - 4) / 4) * 4);
            uint32_t sa = (uint32_t)__cvta_generic_to_shared(
                &Bs[(size_t)buf * BK * LDB_S + krow * LDB_S + n]);
            asm volatile("cp.async.cg.shared.global [%0], [%1], 16, %2;\n"
                         :: "r"(sa), "l"(gp), "r"(bytes));
        }
    };

    const int nIter = (K + BK - 1) / BK;
    loadTiles(0, 0);
    asm volatile("cp.async.commit_group;\n" ::: "memory");

    for (int it = 0; it < nIter; it++) {
        if (it + 1 < nIter) {
            loadTiles((it + 1) & 1, (it + 1) * BK);
            asm volatile("cp.async.commit_group;\n" ::: "memory");
            asm volatile("cp.async.wait_group 1;\n" ::: "memory");
        } else {
            asm volatile("cp.async.wait_group 0;\n" ::: "memory");
        }
        __syncthreads();

        const int buf = it & 1;
        const float* Ab = As + (size_t)buf * BM * LDA_S;
        const float* Bb = Bs + (size_t)buf * BK * LDB_S;
#pragma unroll
        for (int kk = 0; kk < BK / 8; kk++) {
            const int kb = kk * 8;
            float a[MT][4];
            float b[NT][2];
#pragma unroll
            for (int mt = 0; mt < MT; mt++) {
                int r = warpM * WM + mt * 16 + gid;
                a[mt][0] = Ab[r * LDA_S + kb + tig];
                a[mt][1] = Ab[(r + 8) * LDA_S + kb + tig];
                a[mt][2] = Ab[r * LDA_S + kb + tig + 4];
                a[mt][3] = Ab[(r + 8) * LDA_S + kb + tig + 4];
            }
#pragma unroll
            for (int nt = 0; nt < NT; nt++) {
                int c = warpN * WN + nt * 8 + gid;
                b[nt][0] = Bb[(kb + tig) * LDB_S + c];
                b[nt][1] = Bb[(kb + tig + 4) * LDB_S + c];
            }
#pragma unroll
            for (int mt = 0; mt < MT; mt++)
#pragma unroll
                for (int nt = 0; nt < NT; nt++)
                    mma_16x8x8(acc[mt][nt], a[mt], b[nt]);
        }
        __syncthreads();
    }

#pragma unroll
    for (int mt = 0; mt < MT; mt++) {
        int r0 = rowBase + warpM * WM + mt * 16 + gid;
        int r1 = r0 + 8;
        float s0 = 0.0f, s1 = 0.0f;
        if (EPI == 0) {
            s0 = (r0 < M) ? __ldg(&scaleOrBias[r0]) : 0.0f;
            s1 = (r1 < M) ? __ldg(&scaleOrBias[r1]) : 0.0f;
        }
#pragma unroll
        for (int nt = 0; nt < NT; nt++) {
            int c0 = colBase + warpN * WN + nt * 8 + 2 * tig;
            if (c0 >= N) continue;
            if (EPI == 0) {
                if (r0 < M)
                    *(float2*)(C + (size_t)r0 * ldc + c0) =
                        make_float2(s0 * acc[mt][nt][0], s0 * acc[mt][nt][1]);
                if (r1 < M)
                    *(float2*)(C + (size_t)r1 * ldc + c0) =
                        make_float2(s1 * acc[mt][nt][2], s1 * acc[mt][nt][3]);
            } else {
                float2 bb = *(const float2*)(scaleOrBias + c0);
                if (r0 < M) {
                    float2 v;
                    v.x = to_tf32(fmaxf(acc[mt][nt][0] + bb.x, 0.0f));
                    v.y = to_tf32(fmaxf(acc[mt][nt][1] + bb.y, 0.0f));
                    *(float2*)(C + (size_t)r0 * ldc + c0) = v;
                }
                if (r1 < M) {
                    float2 v;
                    v.x = to_tf32(fmaxf(acc[mt][nt][2] + bb.x, 0.0f));
                    v.y = to_tf32(fmaxf(acc[mt][nt][3] + bb.y, 0.0f));
                    *(float2*)(C + (size_t)r1 * ldc + c0) = v;
                }
            }
        }
    }
}

// ---------------- fused aggregation layer 2 ----------------
__global__ void k_agg2(const float2* __restrict__ G2_2, const int* __restrict__ rowptr,
                       const int* __restrict__ esrc, const float* __restrict__ dinv,
                       const float2* __restrict__ b2_2, float2* __restrict__ Z2) {
    int gw = (blockIdx.x * blockDim.x + threadIdx.x) >> 5;
    if (gw >= N_NODES) return;
    int lane = threadIdx.x & 31;
    const int j0 = rowptr[gw], j1 = rowptr[gw + 1];
    float2 acc = G2_2[(size_t)gw * 32 + lane];
    for (int j = j0; j < j1; j++) {
        int s = __ldg(&esrc[j]);
        float2 v = G2_2[(size_t)s * 32 + lane];
        acc.x += v.x; acc.y += v.y;
    }
    float di = dinv[gw];
    float2 b = b2_2[lane];
    Z2[(size_t)gw * 32 + lane] = make_float2(fmaf(di, acc.x, b.x), fmaf(di, acc.y, b.y));
}

// ---------------- decode ----------------
__global__ void k_decode(const float* __restrict__ Z, const int* __restrict__ src,
                         const int* __restrict__ dst, float* __restrict__ out, int E) {
    int gid = blockIdx.x * blockDim.x + threadIdx.x;
    int e = gid >> 3;
    if (e >= E) return;
    int t = gid & 7;
    int s = __ldg(&src[e]);
    int d = __ldg(&dst[e]);
    const float4* zs = (const float4*)(Z + (size_t)s * F2);
    const float4* zd = (const float4*)(Z + (size_t)d * F2);
    float sum = 0.0f;
#pragma unroll
    for (int i = t; i < 16; i += 8) {
        float4 a = zs[i];
        float4 b = zd[i];
        sum += a.x * b.x + a.y * b.y + a.z * b.z + a.w * b.w;
    }
#pragma unroll
    for (int off = 4; off; off >>= 1) sum += __shfl_down_sync(0xffffffffu, sum, off, 8);
    if (t == 0) out[e] = sum;
}

// ---------------- launch ----------------
extern "C" void kernel_launch(void* const* d_in, const int* in_sizes, int n_in,
                              void* d_out, int out_size) {
    const float* x  = (const float*)d_in[0];
    const int*   ei = (const int*)d_in[1];
    const float* W1 = (const float*)d_in[2];
    const float* b1 = (const float*)d_in[3];
    const float* W2 = (const float*)d_in[4];
    const float* b2 = (const float*)d_in[5];
    float* logits = (float*)d_out;

    const int E = in_sizes[1] / 2;
    const int M = N_NODES;
    const int* src = ei;
    const int* dst = ei + E;

    float *dinv, *Y, *out1, *G2, *Z, *W1r, *W2r;
    int *cnt, *rowptr, *cursor, *esrc;
    cudaGetSymbolAddress((void**)&dinv, g_dinv);
    cudaGetSymbolAddress((void**)&Y, g_Y);
    cudaGetSymbolAddress((void**)&out1, g_out1);
    cudaGetSymbolAddress((void**)&G2, g_G2);
    cudaGetSymbolAddress((void**)&Z, g_Z);
    cudaGetSymbolAddress((void**)&W1r, g_W1r);
    cudaGetSymbolAddress((void**)&W2r, g_W2r);
    cudaGetSymbolAddress((void**)&cnt, g_cnt);
    cudaGetSymbolAddress((void**)&rowptr, g_rowptr);
    cudaGetSymbolAddress((void**)&cursor, g_cursor);
    cudaGetSymbolAddress((void**)&esrc, g_esrc);

    // --- CSR build + dinv ---
    k_zero_int<<<(M + 255) / 256, 256>>>(cnt, M);
    k_hist<<<(E + 255) / 256, 256>>>(cnt, dst, E);
    k_scan<<<1, 1024>>>(cnt, rowptr, cursor, M);
    k_dinv<<<(M + 255) / 256, 256>>>(cnt, dinv, M);
    k_fill<<<(E + 255) / 256, 256>>>(cursor, esrc, src, dst, E);

    // --- pre-round weights to tf32 ---
    k_round4<<<((F0 * F1 / 4) + 255) / 256, 256>>>((const float4*)W1, (float4*)W1r, F0 * F1 / 4);
    k_round4<<<((F1 * F2 / 4) + 255) / 256, 256>>>((const float4*)W2, (float4*)W2r, F1 * F2 / 4);

    // --- aggregate x first (conv is linear): Y = dinv ⊙ (Â_rows · x), 2 column passes ---
    k_aggx<<<M, 80>>>((const float4*)x, rowptr, esrc, dinv, (float4*)Y, 0, 75);
    k_aggx<<<M, 80>>>((const float4*)x, rowptr, esrc, dinv, (float4*)Y, 75, 75);

    // --- layer 1 GEMM: out1 = tf32(relu(Y @ W1 + b1)), BK=32, bias epilogue ---
    {
        constexpr int SM1 = (2 * 128 * 36 + 2 * 32 * 136) * 4;  // 71680 B
        cudaFuncSetAttribute((const void*)gemm_tf32_db<128, 128, 32, 32, 64, 1>,
                             cudaFuncAttributeMaxDynamicSharedMemorySize, SM1);
        dim3 grid((F1 + 127) / 128, (M + 127) / 128);
        gemm_tf32_db<128, 128, 32, 32, 64, 1><<<grid, 256, SM1>>>(
            Y, W1r, out1, b1, M, F1, F0, F0, F1, F1);
    }

    // --- layer 2: G2 = dinv ⊙ (out1 @ W2), BK=32 ---
    {
        constexpr int SM2 = (2 * 128 * 36 + 2 * 32 * 72) * 4;   // 55296 B
        cudaFuncSetAttribute((const void*)gemm_tf32_db<128, 64, 32, 32, 32, 0>,
                             cudaFuncAttributeMaxDynamicSharedMemorySize, SM2);
        dim3 grid(1, (M + 127) / 128);
        gemm_tf32_db<128, 64, 32, 32, 32, 0><<<grid, 256, SM2>>>(
            out1, W2r, G2, dinv, M, F2, F1, F1, F2, F2);
    }
    k_agg2<<<(M * 32 + 255) / 256, 256>>>((const float2*)G2, rowptr, esrc, dinv,
                                          (const float2*)b2, (float2*)Z);

    // --- decode ---
    k_decode<<<(E * 8 + 255) / 256, 256>>>(Z, src, dst, logits, E);
}

// round 15
// speedup vs baseline: 5.1208x; 1.2826x over previous
#include <cuda_runtime.h>
#include <cuda_bf16.h>
#include <cstdint>

#define N_NODES 50000
#define E_MAX   400000
#define F0 600
#define F1 628
#define F2 64

// ---------------- scratch ----------------
__device__ float g_dinv[N_NODES];
__device__ __align__(16) __nv_bfloat16 g_Y[(size_t)N_NODES * F0];   // aggregated x (bf16)
__device__ __align__(16) __nv_bfloat16 g_W1T[(size_t)F1 * F0];      // W1 transposed, bf16
__device__ float g_out1[(size_t)N_NODES * F1];
__device__ float g_G2 [(size_t)N_NODES * F2];
__device__ float g_Z  [(size_t)N_NODES * F2];
__device__ float g_W2r[F1 * F2];
__device__ int   g_cnt[N_NODES];
__device__ int   g_rowptr[N_NODES + 1];
__device__ int   g_cursor[N_NODES];
__device__ int   g_esrc[E_MAX];

// ---------------- helpers ----------------
// RNA tf32 rounding REQUIRED on tf32-mma inputs (truncation bias fails: 2.9e-3).
// bf16 path uses RNE (__float2bfloat16_rn) — unbiased, error ~8x tf32 (pred ~5e-4).
__device__ __forceinline__ float to_tf32(float x) {
    uint32_t u;
    asm("cvt.rna.tf32.f32 %0, %1;" : "=r"(u) : "f"(x));
    return __uint_as_float(u);
}
__device__ __forceinline__ void mma_16x8x8(float* d, const float* a, const float* b) {
    asm volatile(
        "mma.sync.aligned.m16n8k8.row.col.f32.tf32.tf32.f32 "
        "{%0,%1,%2,%3}, {%4,%5,%6,%7}, {%8,%9}, {%0,%1,%2,%3};"
        : "+f"(d[0]), "+f"(d[1]), "+f"(d[2]), "+f"(d[3])
        : "r"(__float_as_uint(a[0])), "r"(__float_as_uint(a[1])),
          "r"(__float_as_uint(a[2])), "r"(__float_as_uint(a[3])),
          "r"(__float_as_uint(b[0])), "r"(__float_as_uint(b[1])));
}
__device__ __forceinline__ void mma_bf16_16x8x16(float* d, const uint32_t* a,
                                                 const uint32_t* b) {
    asm volatile(
        "mma.sync.aligned.m16n8k16.row.col.f32.bf16.bf16.f32 "
        "{%0,%1,%2,%3}, {%4,%5,%6,%7}, {%8,%9}, {%0,%1,%2,%3};"
        : "+f"(d[0]), "+f"(d[1]), "+f"(d[2]), "+f"(d[3])
        : "r"(a[0]), "r"(a[1]), "r"(a[2]), "r"(a[3]), "r"(b[0]), "r"(b[1]));
}

// ---------------- CSR build ----------------
__global__ void k_zero_int(int* p, int n) {
    int i = blockIdx.x * blockDim.x + threadIdx.x;
    if (i < n) p[i] = 0;
}
__global__ void k_hist(int* cnt, const int* __restrict__ dst, int e) {
    int i = blockIdx.x * blockDim.x + threadIdx.x;
    if (i < e) atomicAdd(&cnt[dst[i]], 1);
}
__global__ void k_scan(const int* __restrict__ cnt, int* __restrict__ rowptr,
                       int* __restrict__ cursor, int n) {
    __shared__ int part[1024];
    int tid = threadIdx.x;
    int chunk = (n + 1023) / 1024;
    int base = tid * chunk;
    int s = 0;
    for (int i = 0; i < chunk; i++) {
        int idx = base + i;
        if (idx < n) s += cnt[idx];
    }
    part[tid] = s;
    __syncthreads();
    for (int off = 1; off < 1024; off <<= 1) {
        int v = (tid >= off) ? part[tid - off] : 0;
        __syncthreads();
        part[tid] += v;
        __syncthreads();
    }
    int excl = (tid == 0) ? 0 : part[tid - 1];
    for (int i = 0; i < chunk; i++) {
        int idx = base + i;
        if (idx < n) {
            rowptr[idx] = excl;
            cursor[idx] = excl;
            excl += cnt[idx];
        }
    }
    if (tid == 1023) rowptr[n] = part[1023];
}
__global__ void k_dinv(const int* __restrict__ cnt, float* __restrict__ dinv, int n) {
    int i = blockIdx.x * blockDim.x + threadIdx.x;
    if (i < n) dinv[i] = rsqrtf((float)cnt[i] + 1.0f);
}
__global__ void k_fill(int* cursor, int* esrc, const int* __restrict__ src,
                       const int* __restrict__ dst, int e) {
    int i = blockIdx.x * blockDim.x + threadIdx.x;
    if (i >= e) return;
    int pos = atomicAdd(&cursor[dst[i]], 1);
    esrc[pos] = src[i];
}

// ---------------- tf32 pre-round (W2 only) ----------------
__global__ void k_round4(const float4* __restrict__ in, float4* __restrict__ out, int n4) {
    int i = blockIdx.x * blockDim.x + threadIdx.x;
    if (i >= n4) return;
    float4 v = in[i];
    v.x = to_tf32(v.x); v.y = to_tf32(v.y); v.z = to_tf32(v.z); v.w = to_tf32(v.w);
    out[i] = v;
}

// ---------------- W1 transpose -> bf16, n-major [F1][F0] ----------------
__global__ void k_w1t(const float* __restrict__ W, __nv_bfloat16* __restrict__ WT) {
    __shared__ float t[32][33];
    int bx = blockIdx.x * 32;  // n
    int by = blockIdx.y * 32;  // k
    int x = threadIdx.x, y = threadIdx.y;
    for (int i = y; i < 32; i += 8) {
        int k = by + i, n = bx + x;
        t[i][x] = (k < F0 && n < F1) ? W[(size_t)k * F1 + n] : 0.0f;
    }
    __syncthreads();
    for (int i = y; i < 32; i += 8) {
        int n = bx + i, k = by + x;
        if (n < F1 && k < F0) WT[(size_t)n * F0 + k] = __float2bfloat16_rn(t[x][i]);
    }
}

// ---------------- aggregate x (600-dim) -> bf16 Y, column-split ----------------
// Y[d] = bf16( dinv[d] * ( Σ_{s∈in(d)} dinv[s]*x[s] + dinv[d]*x[d] ) )
__global__ void k_aggx(const float4* __restrict__ X4, const int* __restrict__ rowptr,
                       const int* __restrict__ esrc, const float* __restrict__ dinv,
                       __nv_bfloat16* __restrict__ Y, int c0, int nc) {
    const int d = blockIdx.x;
    const int t = threadIdx.x;
    if (t >= nc) return;
    const int col = c0 + t;
    const int j0 = rowptr[d], j1 = rowptr[d + 1];
    const float did = dinv[d];
    float4 xv = X4[(size_t)d * (F0 / 4) + col];
    float4 acc;
    acc.x = did * xv.x; acc.y = did * xv.y; acc.z = did * xv.z; acc.w = did * xv.w;
    for (int j = j0; j < j1; j++) {
        int s = __ldg(&esrc[j]);
        float ds = __ldg(&dinv[s]);
        float4 v = X4[(size_t)s * (F0 / 4) + col];
        acc.x = fmaf(ds, v.x, acc.x);
        acc.y = fmaf(ds, v.y, acc.y);
        acc.z = fmaf(ds, v.z, acc.z);
        acc.w = fmaf(ds, v.w, acc.w);
    }
    __nv_bfloat162 h0 = __float22bfloat162_rn(make_float2(did * acc.x, did * acc.y));
    __nv_bfloat162 h1 = __float22bfloat162_rn(make_float2(did * acc.z, did * acc.w));
    uint2 w;
    w.x = *(uint32_t*)&h0;
    w.y = *(uint32_t*)&h1;
    *(uint2*)(Y + (size_t)d * F0 + col * 4) = w;
}

// ---------------- GEMM1: bf16 mma, out1 = tf32(relu(Y @ W1 + b1)) ----------------
// A = Y [M][600] bf16 row-major; BT = W1T [628][600] bf16 (n-major rows of k).
// BM=128, BN=128, BK=32 halves. Warp grid 4M x 2N; warp tile WM=32 (MT=2 m16),
// WN=64 (NT=8 n8) -> full 128x128 coverage (R13 fix: was 2Mx4N, OOB smem read).
// smem rows padded to 40 halves (conflict-free). Double-buffered cp.async.
#define LDH 40
__global__ __launch_bounds__(256, 2)
void gemm1_bf16(const __nv_bfloat16* __restrict__ A,
                const __nv_bfloat16* __restrict__ BT,
                float* __restrict__ C, const float* __restrict__ bias, int M) {
    constexpr int BM = 128, BN = 128, BK = 32;
    constexpr int MT = 2, NT = 8;
    extern __shared__ __nv_bfloat16 smh[];
    __nv_bfloat16* As = smh;                     // [2][BM][LDH]
    __nv_bfloat16* Bs = smh + 2 * BM * LDH;      // [2][BN][LDH]

    const int tid = threadIdx.x;
    const int lane = tid & 31;
    const int warp = tid >> 5;
    const int warpM = warp >> 1;     // 0..3  (4 M-warps x 32 rows = 128)
    const int warpN = warp & 1;      // 0..1  (2 N-warps x 64 cols = 128)
    const int gid = lane >> 2;
    const int tig = lane & 3;
    const int rowBase = blockIdx.y * BM;
    const int colBase = blockIdx.x * BN;

    float acc[MT][NT][4];
#pragma unroll
    for (int i = 0; i < MT; i++)
#pragma unroll
        for (int j = 0; j < NT; j++)
#pragma unroll
            for (int q = 0; q < 4; q++) acc[i][j][q] = 0.0f;

    auto loadTiles = [&](int buf, int k0) {
        // A: 128 rows x 4 chunks (8 halves each)
#pragma unroll
        for (int i = 0; i < 2; i++) {
            int f = tid + i * 256;
            int row = f >> 2, ch = f & 3;
            int grow = min(rowBase + row, M - 1);
            int gk = min(k0 + ch * 8, F0 - 8);    // clamp; B zfill guards math
            const __nv_bfloat16* gp = A + (size_t)grow * F0 + gk;
            uint32_t sa = (uint32_t)__cvta_generic_to_shared(
                As + (size_t)buf * BM * LDH + row * LDH + ch * 8);
            asm volatile("cp.async.cg.shared.global [%0], [%1], 16;\n"
                         :: "r"(sa), "l"(gp));
        }
        // B: 128 n-rows x 4 chunks
#pragma unroll
        for (int i = 0; i < 2; i++) {
            int f = tid + i * 256;
            int n = f >> 2, ch = f & 3;
            int gn = colBase + n;
            int gk = k0 + ch * 8;
            int bytes = (gn < F1 && gk < F0) ? 16 : 0;   // zfill at K/N edges
            const __nv_bfloat16* gp = BT + (size_t)min(gn, F1 - 1) * F0 + min(gk, F0 - 8);
            uint32_t sa = (uint32_t)__cvta_generic_to_shared(
                Bs + (size_t)buf * BN * LDH + n * LDH + ch * 8);
            asm volatile("cp.async.cg.shared.global [%0], [%1], 16, %2;\n"
                         :: "r"(sa), "l"(gp), "r"(bytes));
        }
    };

    const int nIter = (F0 + BK - 1) / BK;   // 19
    loadTiles(0, 0);
    asm volatile("cp.async.commit_group;\n" ::: "memory");

    for (int it = 0; it < nIter; it++) {
        if (it + 1 < nIter) {
            loadTiles((it + 1) & 1, (it + 1) * BK);
            asm volatile("cp.async.commit_group;\n" ::: "memory");
            asm volatile("cp.async.wait_group 1;\n" ::: "memory");
        } else {
            asm volatile("cp.async.wait_group 0;\n" ::: "memory");
        }
        __syncthreads();

        const int buf = it & 1;
        const __nv_bfloat16* Ab = As + (size_t)buf * BM * LDH;
        const __nv_bfloat16* Bb = Bs + (size_t)buf * BN * LDH;
#pragma unroll
        for (int kk = 0; kk < 2; kk++) {
            const int kb = kk * 16;
            uint32_t a[MT][4], b[NT][2];
#pragma unroll
            for (int mt = 0; mt < MT; mt++) {
                int r = warpM * 32 + mt * 16 + gid;
                a[mt][0] = *(const uint32_t*)(Ab + r * LDH + kb + 2 * tig);
                a[mt][1] = *(const uint32_t*)(Ab + (r + 8) * LDH + kb + 2 * tig);
                a[mt][2] = *(const uint32_t*)(Ab + r * LDH + kb + 2 * tig + 8);
                a[mt][3] = *(const uint32_t*)(Ab + (r + 8) * LDH + kb + 2 * tig + 8);
            }
#pragma unroll
            for (int nt = 0; nt < NT; nt++) {
                int c = warpN * 64 + nt * 8 + gid;
                b[nt][0] = *(const uint32_t*)(Bb + c * LDH + kb + 2 * tig);
                b[nt][1] = *(const uint32_t*)(Bb + c * LDH + kb + 2 * tig + 8);
            }
#pragma unroll
            for (int mt = 0; mt < MT; mt++)
#pragma unroll
                for (int nt = 0; nt < NT; nt++)
                    mma_bf16_16x8x16(acc[mt][nt], a[mt], b[nt]);
        }
        __syncthreads();
    }

    // epilogue: bias + relu + tf32-RNA round (for tf32 GEMM2)
#pragma unroll
    for (int mt = 0; mt < MT; mt++) {
        int r0 = rowBase + warpM * 32 + mt * 16 + gid;
        int r1 = r0 + 8;
#pragma unroll
        for (int nt = 0; nt < NT; nt++) {
            int c0 = colBase + warpN * 64 + nt * 8 + 2 * tig;
            if (c0 >= F1) continue;
            float2 bb = *(const float2*)(bias + c0);
            if (r0 < M) {
                float2 v;
                v.x = to_tf32(fmaxf(acc[mt][nt][0] + bb.x, 0.0f));
                v.y = to_tf32(fmaxf(acc[mt][nt][1] + bb.y, 0.0f));
                *(float2*)(C + (size_t)r0 * F1 + c0) = v;
            }
            if (r1 < M) {
                float2 v;
                v.x = to_tf32(fmaxf(acc[mt][nt][2] + bb.x, 0.0f));
                v.y = to_tf32(fmaxf(acc[mt][nt][3] + bb.y, 0.0f));
                *(float2*)(C + (size_t)r1 * F1 + c0) = v;
            }
        }
    }
}

// ---------------- tf32 GEMM (layer 2): C = rowScale ⊙ (A@B) ----------------
template <int BM, int BN, int BK, int WM, int WN>
__global__ __launch_bounds__((BM / WM) * (BN / WN) * 32, 2)
void gemm_tf32_db(const float* __restrict__ A, const float* __restrict__ B,
                  float* __restrict__ C, const float* __restrict__ rowScale,
                  int M, int N, int K, int lda, int ldb, int ldc) {
    constexpr int WARPS_M = BM / WM;
    constexpr int WARPS_N = BN / WN;
    constexpr int NTHREADS = WARPS_M * WARPS_N * 32;
    constexpr int MT = WM / 16;
    constexpr int NT = WN / 8;
    constexpr int LDA_S = BK + 4;
    constexpr int LDB_S = BN + 8;
    constexpr int LA = (BM * BK / 4) / NTHREADS;
    constexpr int LB = (BK * BN / 4) / NTHREADS;

    extern __shared__ float sm[];
    float* As = sm;
    float* Bs = sm + 2 * BM * LDA_S;

    const int tid = threadIdx.x;
    const int lane = tid & 31;
    const int warp = tid >> 5;
    const int warpM = warp / WARPS_N;
    const int warpN = warp % WARPS_N;
    const int gid = lane >> 2;
    const int tig = lane & 3;
    const int rowBase = blockIdx.y * BM;
    const int colBase = blockIdx.x * BN;

    float acc[MT][NT][4];
#pragma unroll
    for (int i = 0; i < MT; i++)
#pragma unroll
        for (int j = 0; j < NT; j++)
#pragma unroll
            for (int q = 0; q < 4; q++) acc[i][j][q] = 0.0f;

    auto loadTiles = [&](int buf, int k0) {
#pragma unroll
        for (int i = 0; i < LA; i++) {
            int f = tid + i * NTHREADS;
            int row = f / (BK / 4);
            int k = (f % (BK / 4)) * 4;
            int grow = min(rowBase + row, M - 1);
            int gk = min(k0 + k, ((K - 4) / 4) * 4);
            const float* gp = A + (size_t)grow * lda + gk;
            uint32_t sa = (uint32_t)__cvta_generic_to_shared(
                &As[(size_t)buf * BM * LDA_S + row * LDA_S + k]);
            asm volatile("cp.async.cg.shared.global [%0], [%1], 16;\n"
                         :: "r"(sa), "l"(gp));
        }
#pragma unroll
        for (int i = 0; i < LB; i++) {
            int f = tid + i * NTHREADS;
            int krow = f / (BN / 4);
            int n = (f % (BN / 4)) * 4;
            int gk = k0 + krow;
            int gcol = colBase + n;
            int bytes = (gk < K && gcol < N) ? 16 : 0;
            const float* gp = B + (size_t)min(gk, K - 1) * ldb + min(gcol, ((N - 4) / 4) * 4);
            uint32_t sa = (uint32_t)__cvta_generic_to_shared(
                &Bs[(size_t)buf * BK * LDB_S + krow * LDB_S + n]);
            asm volatile("cp.async.cg.shared.global [%0], [%1], 16, %2;\n"
                         :: "r"(sa), "l"(gp), "r"(bytes));
        }
    };

    const int nIter = (K + BK - 1) / BK;
    loadTiles(0, 0);
    asm volatile("cp.async.commit_group;\n" ::: "memory");

    for (int it = 0; it < nIter; it++) {
        if (it + 1 < nIter) {
            loadTiles((it + 1) & 1, (it + 1) * BK);
            asm volatile("cp.async.commit_group;\n" ::: "memory");
            asm volatile("cp.async.wait_group 1;\n" ::: "memory");
        } else {
            asm volatile("cp.async.wait_group 0;\n" ::: "memory");
        }
        __syncthreads();

        const int buf = it & 1;
        const float* Ab = As + (size_t)buf * BM * LDA_S;
        const float* Bb = Bs + (size_t)buf * BK * LDB_S;
#pragma unroll
        for (int kk = 0; kk < BK / 8; kk++) {
            const int kb = kk * 8;
            float a[MT][4];
            float b[NT][2];
#pragma unroll
            for (int mt = 0; mt < MT; mt++) {
                int r = warpM * WM + mt * 16 + gid;
                a[mt][0] = Ab[r * LDA_S + kb + tig];
                a[mt][1] = Ab[(r + 8) * LDA_S + kb + tig];
                a[mt][2] = Ab[r * LDA_S + kb + tig + 4];
                a[mt][3] = Ab[(r + 8) * LDA_S + kb + tig + 4];
            }
#pragma unroll
            for (int nt = 0; nt < NT; nt++) {
                int c = warpN * WN + nt * 8 + gid;
                b[nt][0] = Bb[(kb + tig) * LDB_S + c];
                b[nt][1] = Bb[(kb + tig + 4) * LDB_S + c];
            }
#pragma unroll
            for (int mt = 0; mt < MT; mt++)
#pragma unroll
                for (int nt = 0; nt < NT; nt++)
                    mma_16x8x8(acc[mt][nt], a[mt], b[nt]);
        }
        __syncthreads();
    }

#pragma unroll
    for (int mt = 0; mt < MT; mt++) {
        int r0 = rowBase + warpM * WM + mt * 16 + gid;
        int r1 = r0 + 8;
        float s0 = (r0 < M) ? __ldg(&rowScale[r0]) : 0.0f;
        float s1 = (r1 < M) ? __ldg(&rowScale[r1]) : 0.0f;
#pragma unroll
        for (int nt = 0; nt < NT; nt++) {
            int c0 = colBase + warpN * WN + nt * 8 + 2 * tig;
            if (c0 >= N) continue;
            if (r0 < M)
                *(float2*)(C + (size_t)r0 * ldc + c0) =
                    make_float2(s0 * acc[mt][nt][0], s0 * acc[mt][nt][1]);
            if (r1 < M)
                *(float2*)(C + (size_t)r1 * ldc + c0) =
                    make_float2(s1 * acc[mt][nt][2], s1 * acc[mt][nt][3]);
        }
    }
}

// ---------------- fused aggregation layer 2 ----------------
__global__ void k_agg2(const float2* __restrict__ G2_2, const int* __restrict__ rowptr,
                       const int* __restrict__ esrc, const float* __restrict__ dinv,
                       const float2* __restrict__ b2_2, float2* __restrict__ Z2) {
    int gw = (blockIdx.x * blockDim.x + threadIdx.x) >> 5;
    if (gw >= N_NODES) return;
    int lane = threadIdx.x & 31;
    const int j0 = rowptr[gw], j1 = rowptr[gw + 1];
    float2 acc = G2_2[(size_t)gw * 32 + lane];
    for (int j = j0; j < j1; j++) {
        int s = __ldg(&esrc[j]);
        float2 v = G2_2[(size_t)s * 32 + lane];
        acc.x += v.x; acc.y += v.y;
    }
    float di = dinv[gw];
    float2 b = b2_2[lane];
    Z2[(size_t)gw * 32 + lane] = make_float2(fmaf(di, acc.x, b.x), fmaf(di, acc.y, b.y));
}

// ---------------- decode ----------------
__global__ void k_decode(const float* __restrict__ Z, const int* __restrict__ src,
                         const int* __restrict__ dst, float* __restrict__ out, int E) {
    int gid = blockIdx.x * blockDim.x + threadIdx.x;
    int e = gid >> 3;
    if (e >= E) return;
    int t = gid & 7;
    int s = __ldg(&src[e]);
    int d = __ldg(&dst[e]);
    const float4* zs = (const float4*)(Z + (size_t)s * F2);
    const float4* zd = (const float4*)(Z + (size_t)d * F2);
    float sum = 0.0f;
#pragma unroll
    for (int i = t; i < 16; i += 8) {
        float4 a = zs[i];
        float4 b = zd[i];
        sum += a.x * b.x + a.y * b.y + a.z * b.z + a.w * b.w;
    }
#pragma unroll
    for (int off = 4; off; off >>= 1) sum += __shfl_down_sync(0xffffffffu, sum, off, 8);
    if (t == 0) out[e] = sum;
}

// ---------------- launch ----------------
extern "C" void kernel_launch(void* const* d_in, const int* in_sizes, int n_in,
                              void* d_out, int out_size) {
    const float* x  = (const float*)d_in[0];
    const int*   ei = (const int*)d_in[1];
    const float* W1 = (const float*)d_in[2];
    const float* b1 = (const float*)d_in[3];
    const float* W2 = (const float*)d_in[4];
    const float* b2 = (const float*)d_in[5];
    float* logits = (float*)d_out;

    const int E = in_sizes[1] / 2;
    const int M = N_NODES;
    const int* src = ei;
    const int* dst = ei + E;

    float *dinv, *out1, *G2, *Z, *W2r;
    __nv_bfloat16 *Y, *W1T;
    int *cnt, *rowptr, *cursor, *esrc;
    cudaGetSymbolAddress((void**)&dinv, g_dinv);
    cudaGetSymbolAddress((void**)&Y, g_Y);
    cudaGetSymbolAddress((void**)&W1T, g_W1T);
    cudaGetSymbolAddress((void**)&out1, g_out1);
    cudaGetSymbolAddress((void**)&G2, g_G2);
    cudaGetSymbolAddress((void**)&Z, g_Z);
    cudaGetSymbolAddress((void**)&W2r, g_W2r);
    cudaGetSymbolAddress((void**)&cnt, g_cnt);
    cudaGetSymbolAddress((void**)&rowptr, g_rowptr);
    cudaGetSymbolAddress((void**)&cursor, g_cursor);
    cudaGetSymbolAddress((void**)&esrc, g_esrc);

    // --- CSR build + dinv ---
    k_zero_int<<<(M + 255) / 256, 256>>>(cnt, M);
    k_hist<<<(E + 255) / 256, 256>>>(cnt, dst, E);
    k_scan<<<1, 1024>>>(cnt, rowptr, cursor, M);
    k_dinv<<<(M + 255) / 256, 256>>>(cnt, dinv, M);
    k_fill<<<(E + 255) / 256, 256>>>(cursor, esrc, src, dst, E);

    // --- weight prep: W1 -> bf16 transpose, W2 -> tf32 round ---
    {
        dim3 grid((F1 + 31) / 32, (F0 + 31) / 32);
        k_w1t<<<grid, dim3(32, 8)>>>(W1, W1T);
    }
    k_round4<<<((F1 * F2 / 4) + 255) / 256, 256>>>((const float4*)W2, (float4*)W2r,
                                                   F1 * F2 / 4);

    // --- aggregate x first (conv linearity), bf16 output, 2 column passes ---
    k_aggx<<<M, 80>>>((const float4*)x, rowptr, esrc, dinv, Y, 0, 75);
    k_aggx<<<M, 80>>>((const float4*)x, rowptr, esrc, dinv, Y, 75, 75);

    // --- layer 1 GEMM (bf16 mma): out1 = tf32(relu(Y @ W1 + b1)) ---
    {
        constexpr int SM1 = 2 * (128 * LDH + 128 * LDH) * 2;   // 40960 B
        cudaFuncSetAttribute((const void*)gemm1_bf16,
                             cudaFuncAttributeMaxDynamicSharedMemorySize, SM1);
        dim3 grid((F1 + 127) / 128, (M + 127) / 128);
        gemm1_bf16<<<grid, 256, SM1>>>(Y, W1T, out1, b1, M);
    }

    // --- layer 2 (tf32): G2 = dinv ⊙ (out1 @ W2), BK=32 ---
    {
        constexpr int SM2 = (2 * 128 * 36 + 2 * 32 * 72) * 4;   // 55296 B
        cudaFuncSetAttribute((const void*)gemm_tf32_db<128, 64, 32, 32, 32>,
                             cudaFuncAttributeMaxDynamicSharedMemorySize, SM2);
        dim3 grid(1, (M + 127) / 128);
        gemm_tf32_db<128, 64, 32, 32, 32><<<grid, 256, SM2>>>(
            out1, W2r, G2, dinv, M, F2, F1, F1, F2, F2);
    }
    k_agg2<<<(M * 32 + 255) / 256, 256>>>((const float2*)G2, rowptr, esrc, dinv,
                                          (const float2*)b2, (float2*)Z);

    // --- decode ---
    k_decode<<<(E * 8 + 255) / 256, 256>>>(Z, src, dst, logits, E);
}

// round 16
// speedup vs baseline: 5.3363x; 1.0421x over previous
#include <cuda_runtime.h>
#include <cuda_bf16.h>
#include <cstdint>

#define N_NODES 50000
#define E_MAX   400000
#define F0 600
#define F1 628
#define F1P 632   /* out1/W2T padded K (mult of 8), pad zeroed */
#define F2 64

// ---------------- scratch ----------------
__device__ float g_dinv[N_NODES];
__device__ __align__(16) __nv_bfloat16 g_Y[(size_t)N_NODES * F0];     // aggregated x (bf16)
__device__ __align__(16) __nv_bfloat16 g_W1T[(size_t)F1 * F0];        // W1^T bf16 [628][600]
__device__ __align__(16) __nv_bfloat16 g_out1[(size_t)N_NODES * F1P]; // relu out, bf16, padded
__device__ __align__(16) __nv_bfloat16 g_W2T[(size_t)F2 * F1P];       // W2^T bf16 [64][632]
__device__ float g_G2 [(size_t)N_NODES * F2];
__device__ float g_Z  [(size_t)N_NODES * F2];
__device__ int   g_cnt[N_NODES];
__device__ int   g_rowptr[N_NODES + 1];
__device__ int   g_cursor[N_NODES];
__device__ int   g_esrc[E_MAX];

// ---------------- helpers ----------------
__device__ __forceinline__ void mma_bf16_16x8x16(float* d, const uint32_t* a,
                                                 const uint32_t* b) {
    asm volatile(
        "mma.sync.aligned.m16n8k16.row.col.f32.bf16.bf16.f32 "
        "{%0,%1,%2,%3}, {%4,%5,%6,%7}, {%8,%9}, {%0,%1,%2,%3};"
        : "+f"(d[0]), "+f"(d[1]), "+f"(d[2]), "+f"(d[3])
        : "r"(a[0]), "r"(a[1]), "r"(a[2]), "r"(a[3]), "r"(b[0]), "r"(b[1]));
}

// ---------------- CSR build ----------------
__global__ void k_zero_int(int* p, int n) {
    int i = blockIdx.x * blockDim.x + threadIdx.x;
    if (i < n) p[i] = 0;
}
__global__ void k_hist(int* cnt, const int* __restrict__ dst, int e) {
    int i = blockIdx.x * blockDim.x + threadIdx.x;
    if (i < e) atomicAdd(&cnt[dst[i]], 1);
}
__global__ void k_scan(const int* __restrict__ cnt, int* __restrict__ rowptr,
                       int* __restrict__ cursor, int n) {
    __shared__ int part[1024];
    int tid = threadIdx.x;
    int chunk = (n + 1023) / 1024;
    int base = tid * chunk;
    int s = 0;
    for (int i = 0; i < chunk; i++) {
        int idx = base + i;
        if (idx < n) s += cnt[idx];
    }
    part[tid] = s;
    __syncthreads();
    for (int off = 1; off < 1024; off <<= 1) {
        int v = (tid >= off) ? part[tid - off] : 0;
        __syncthreads();
        part[tid] += v;
        __syncthreads();
    }
    int excl = (tid == 0) ? 0 : part[tid - 1];
    for (int i = 0; i < chunk; i++) {
        int idx = base + i;
        if (idx < n) {
            rowptr[idx] = excl;
            cursor[idx] = excl;
            excl += cnt[idx];
        }
    }
    if (tid == 1023) rowptr[n] = part[1023];
}
__global__ void k_dinv(const int* __restrict__ cnt, float* __restrict__ dinv, int n) {
    int i = blockIdx.x * blockDim.x + threadIdx.x;
    if (i < n) dinv[i] = rsqrtf((float)cnt[i] + 1.0f);
}
__global__ void k_fill(int* cursor, int* esrc, const int* __restrict__ src,
                       const int* __restrict__ dst, int e) {
    int i = blockIdx.x * blockDim.x + threadIdx.x;
    if (i >= e) return;
    int pos = atomicAdd(&cursor[dst[i]], 1);
    esrc[pos] = src[i];
}

// ---------------- W1 transpose -> bf16, n-major [F1][F0] ----------------
__global__ void k_w1t(const float* __restrict__ W, __nv_bfloat16* __restrict__ WT) {
    __shared__ float t[32][33];
    int bx = blockIdx.x * 32;  // n
    int by = blockIdx.y * 32;  // k
    int x = threadIdx.x, y = threadIdx.y;
    for (int i = y; i < 32; i += 8) {
        int k = by + i, n = bx + x;
        t[i][x] = (k < F0 && n < F1) ? W[(size_t)k * F1 + n] : 0.0f;
    }
    __syncthreads();
    for (int i = y; i < 32; i += 8) {
        int n = bx + i, k = by + x;
        if (n < F1 && k < F0) WT[(size_t)n * F0 + k] = __float2bfloat16_rn(t[x][i]);
    }
}

// ---------------- W2 transpose -> bf16 [F2][F1P], zero-padded K tail ----------------
__global__ void k_w2t(const float* __restrict__ W2, __nv_bfloat16* __restrict__ WT) {
    int idx = blockIdx.x * blockDim.x + threadIdx.x;
    if (idx >= F2 * F1P) return;
    int n = idx / F1P;
    int k = idx - n * F1P;
    WT[idx] = (k < F1) ? __float2bfloat16_rn(W2[(size_t)k * F2 + n]) : __nv_bfloat16(0.0f);
}

// ---------------- aggregate x (600-dim) -> bf16 Y, column-split ----------------
// Y[d] = bf16( dinv[d] * ( Σ_{s∈in(d)} dinv[s]*x[s] + dinv[d]*x[d] ) )
__global__ void k_aggx(const float4* __restrict__ X4, const int* __restrict__ rowptr,
                       const int* __restrict__ esrc, const float* __restrict__ dinv,
                       __nv_bfloat16* __restrict__ Y, int c0, int nc) {
    const int d = blockIdx.x;
    const int t = threadIdx.x;
    if (t >= nc) return;
    const int col = c0 + t;
    const int j0 = rowptr[d], j1 = rowptr[d + 1];
    const float did = dinv[d];
    float4 xv = X4[(size_t)d * (F0 / 4) + col];
    float4 acc;
    acc.x = did * xv.x; acc.y = did * xv.y; acc.z = did * xv.z; acc.w = did * xv.w;
    for (int j = j0; j < j1; j++) {
        int s = __ldg(&esrc[j]);
        float ds = __ldg(&dinv[s]);
        float4 v = X4[(size_t)s * (F0 / 4) + col];
        acc.x = fmaf(ds, v.x, acc.x);
        acc.y = fmaf(ds, v.y, acc.y);
        acc.z = fmaf(ds, v.z, acc.z);
        acc.w = fmaf(ds, v.w, acc.w);
    }
    __nv_bfloat162 h0 = __float22bfloat162_rn(make_float2(did * acc.x, did * acc.y));
    __nv_bfloat162 h1 = __float22bfloat162_rn(make_float2(did * acc.z, did * acc.w));
    uint2 w;
    w.x = *(uint32_t*)&h0;
    w.y = *(uint32_t*)&h1;
    *(uint2*)(Y + (size_t)d * F0 + col * 4) = w;
}

// ---------------- GEMM1: bf16 mma, out1 = bf16(relu(Y @ W1 + b1)) ----------------
// Warp grid 4M x 2N (WM=32, WN=64) covers 128x128 exactly. smem rows LDH=40.
#define LDH 40
__global__ __launch_bounds__(256, 2)
void gemm1_bf16(const __nv_bfloat16* __restrict__ A,
                const __nv_bfloat16* __restrict__ BT,
                __nv_bfloat16* __restrict__ C, const float* __restrict__ bias, int M) {
    constexpr int BM = 128, BN = 128, BK = 32;
    constexpr int MT = 2, NT = 8;
    extern __shared__ __nv_bfloat16 smh[];
    __nv_bfloat16* As = smh;                     // [2][BM][LDH]
    __nv_bfloat16* Bs = smh + 2 * BM * LDH;      // [2][BN][LDH]

    const int tid = threadIdx.x;
    const int lane = tid & 31;
    const int warp = tid >> 5;
    const int warpM = warp >> 1;     // 0..3
    const int warpN = warp & 1;      // 0..1
    const int gid = lane >> 2;
    const int tig = lane & 3;
    const int rowBase = blockIdx.y * BM;
    const int colBase = blockIdx.x * BN;

    float acc[MT][NT][4];
#pragma unroll
    for (int i = 0; i < MT; i++)
#pragma unroll
        for (int j = 0; j < NT; j++)
#pragma unroll
            for (int q = 0; q < 4; q++) acc[i][j][q] = 0.0f;

    auto loadTiles = [&](int buf, int k0) {
#pragma unroll
        for (int i = 0; i < 2; i++) {
            int f = tid + i * 256;
            int row = f >> 2, ch = f & 3;
            int grow = min(rowBase + row, M - 1);
            int gk = min(k0 + ch * 8, F0 - 8);
            const __nv_bfloat16* gp = A + (size_t)grow * F0 + gk;
            uint32_t sa = (uint32_t)__cvta_generic_to_shared(
                As + (size_t)buf * BM * LDH + row * LDH + ch * 8);
            asm volatile("cp.async.cg.shared.global [%0], [%1], 16;\n"
                         :: "r"(sa), "l"(gp));
        }
#pragma unroll
        for (int i = 0; i < 2; i++) {
            int f = tid + i * 256;
            int n = f >> 2, ch = f & 3;
            int gn = colBase + n;
            int gk = k0 + ch * 8;
            int bytes = (gn < F1 && gk < F0) ? 16 : 0;
            const __nv_bfloat16* gp = BT + (size_t)min(gn, F1 - 1) * F0 + min(gk, F0 - 8);
            uint32_t sa = (uint32_t)__cvta_generic_to_shared(
                Bs + (size_t)buf * BN * LDH + n * LDH + ch * 8);
            asm volatile("cp.async.cg.shared.global [%0], [%1], 16, %2;\n"
                         :: "r"(sa), "l"(gp), "r"(bytes));
        }
    };

    const int nIter = (F0 + BK - 1) / BK;   // 19
    loadTiles(0, 0);
    asm volatile("cp.async.commit_group;\n" ::: "memory");

    for (int it = 0; it < nIter; it++) {
        if (it + 1 < nIter) {
            loadTiles((it + 1) & 1, (it + 1) * BK);
            asm volatile("cp.async.commit_group;\n" ::: "memory");
            asm volatile("cp.async.wait_group 1;\n" ::: "memory");
        } else {
            asm volatile("cp.async.wait_group 0;\n" ::: "memory");
        }
        __syncthreads();

        const int buf = it & 1;
        const __nv_bfloat16* Ab = As + (size_t)buf * BM * LDH;
        const __nv_bfloat16* Bb = Bs + (size_t)buf * BN * LDH;
#pragma unroll
        for (int kk = 0; kk < 2; kk++) {
            const int kb = kk * 16;
            uint32_t a[MT][4], b[NT][2];
#pragma unroll
            for (int mt = 0; mt < MT; mt++) {
                int r = warpM * 32 + mt * 16 + gid;
                a[mt][0] = *(const uint32_t*)(Ab + r * LDH + kb + 2 * tig);
                a[mt][1] = *(const uint32_t*)(Ab + (r + 8) * LDH + kb + 2 * tig);
                a[mt][2] = *(const uint32_t*)(Ab + r * LDH + kb + 2 * tig + 8);
                a[mt][3] = *(const uint32_t*)(Ab + (r + 8) * LDH + kb + 2 * tig + 8);
            }
#pragma unroll
            for (int nt = 0; nt < NT; nt++) {
                int c = warpN * 64 + nt * 8 + gid;
                b[nt][0] = *(const uint32_t*)(Bb + c * LDH + kb + 2 * tig);
                b[nt][1] = *(const uint32_t*)(Bb + c * LDH + kb + 2 * tig + 8);
            }
#pragma unroll
            for (int mt = 0; mt < MT; mt++)
#pragma unroll
                for (int nt = 0; nt < NT; nt++)
                    mma_bf16_16x8x16(acc[mt][nt], a[mt], b[nt]);
        }
        __syncthreads();
    }

    // epilogue: bias + relu -> bf16 out1 (stride F1P; pad cols 628..631 zeroed)
#pragma unroll
    for (int mt = 0; mt < MT; mt++) {
        int r0 = rowBase + warpM * 32 + mt * 16 + gid;
        int r1 = r0 + 8;
#pragma unroll
        for (int nt = 0; nt < NT; nt++) {
            int c0 = colBase + warpN * 64 + nt * 8 + 2 * tig;
            if (c0 >= F1P) continue;
            float2 bb = (c0 < F1) ? *(const float2*)(bias + c0) : make_float2(0.f, 0.f);
            if (r0 < M) {
                float2 v = make_float2(0.f, 0.f);
                if (c0 < F1) {
                    v.x = fmaxf(acc[mt][nt][0] + bb.x, 0.0f);
                    v.y = fmaxf(acc[mt][nt][1] + bb.y, 0.0f);
                }
                __nv_bfloat162 h = __float22bfloat162_rn(v);
                *(uint32_t*)(C + (size_t)r0 * F1P + c0) = *(uint32_t*)&h;
            }
            if (r1 < M) {
                float2 v = make_float2(0.f, 0.f);
                if (c0 < F1) {
                    v.x = fmaxf(acc[mt][nt][2] + bb.x, 0.0f);
                    v.y = fmaxf(acc[mt][nt][3] + bb.y, 0.0f);
                }
                __nv_bfloat162 h = __float22bfloat162_rn(v);
                *(uint32_t*)(C + (size_t)r1 * F1P + c0) = *(uint32_t*)&h;
            }
        }
    }
}

// ---------------- GEMM2: bf16 mma, G2 = dinv ⊙ (out1 @ W2) ----------------
// A = out1 [M][632] bf16; BT = W2T [64][632] bf16. BM=128, BN=64, BK=32.
// Warp grid 4M x 2N: WM=32 (MT=2), WN=32 (NT=4). K=632 (pad zeroed both sides).
__global__ __launch_bounds__(256, 2)
void gemm2_bf16(const __nv_bfloat16* __restrict__ A,
                const __nv_bfloat16* __restrict__ BT,
                float* __restrict__ C, const float* __restrict__ dinv, int M) {
    constexpr int BM = 128, BN = 64, BK = 32;
    constexpr int MT = 2, NT = 4;
    extern __shared__ __nv_bfloat16 smh[];
    __nv_bfloat16* As = smh;                     // [2][BM][LDH]
    __nv_bfloat16* Bs = smh + 2 * BM * LDH;      // [2][BN][LDH]

    const int tid = threadIdx.x;
    const int lane = tid & 31;
    const int warp = tid >> 5;
    const int warpM = warp >> 1;     // 0..3
    const int warpN = warp & 1;      // 0..1
    const int gid = lane >> 2;
    const int tig = lane & 3;
    const int rowBase = blockIdx.y * BM;

    float acc[MT][NT][4];
#pragma unroll
    for (int i = 0; i < MT; i++)
#pragma unroll
        for (int j = 0; j < NT; j++)
#pragma unroll
            for (int q = 0; q < 4; q++) acc[i][j][q] = 0.0f;

    auto loadTiles = [&](int buf, int k0) {
        // A: 128 rows x 4 chunks
#pragma unroll
        for (int i = 0; i < 2; i++) {
            int f = tid + i * 256;
            int row = f >> 2, ch = f & 3;
            int grow = min(rowBase + row, M - 1);
            int gk = min(k0 + ch * 8, F1P - 8);   // clamp; B zero-pad kills garbage
            const __nv_bfloat16* gp = A + (size_t)grow * F1P + gk;
            uint32_t sa = (uint32_t)__cvta_generic_to_shared(
                As + (size_t)buf * BM * LDH + row * LDH + ch * 8);
            asm volatile("cp.async.cg.shared.global [%0], [%1], 16;\n"
                         :: "r"(sa), "l"(gp));
        }
        // B: 64 n-rows x 4 chunks = 256 loads (1 iter)
        {
            int n = tid >> 2, ch = tid & 3;
            int gk = min(k0 + ch * 8, F1P - 8);
            const __nv_bfloat16* gp = BT + (size_t)n * F1P + gk;
            uint32_t sa = (uint32_t)__cvta_generic_to_shared(
                Bs + (size_t)buf * BN * LDH + n * LDH + ch * 8);
            asm volatile("cp.async.cg.shared.global [%0], [%1], 16;\n"
                         :: "r"(sa), "l"(gp));
        }
    };

    const int nIter = (F1P + BK - 1) / BK;   // 20 (last chunk 608..639 -> clamped dup,
                                             // but W2T cols 628..631 are zero and A pad
                                             // zero, dup slots multiply by zero B)
    // NOTE: clamping duplicates k=624..631 into slots 632..639 on BOTH A and B.
    // B slot 632..639 holds W2T[624..631] (nonzero!) -> would double-count.
    // Avoid: last iteration uses BK=24? Simpler: nIter covers K=632 exactly since
    // 632 = 19*32 + 24; we zero smem slots beyond 632 via a guard on B load instead.
    // Implemented: see bytes guard below (re-written loads).
    (void)0;

    // (re-do loads with proper guards)
    auto loadTiles2 = [&](int buf, int k0) {
#pragma unroll
        for (int i = 0; i < 2; i++) {
            int f = tid + i * 256;
            int row = f >> 2, ch = f & 3;
            int grow = min(rowBase + row, M - 1);
            int gk = k0 + ch * 8;
            int bytes = (gk < F1P) ? 16 : 0;
            const __nv_bfloat16* gp = A + (size_t)grow * F1P + min(gk, F1P - 8);
            uint32_t sa = (uint32_t)__cvta_generic_to_shared(
                As + (size_t)buf * BM * LDH + row * LDH + ch * 8);
            asm volatile("cp.async.cg.shared.global [%0], [%1], 16, %2;\n"
                         :: "r"(sa), "l"(gp), "r"(bytes));
        }
        {
            int n = tid >> 2, ch = tid & 3;
            int gk = k0 + ch * 8;
            int bytes = (gk < F1P) ? 16 : 0;
            const __nv_bfloat16* gp = BT + (size_t)n * F1P + min(gk, F1P - 8);
            uint32_t sa = (uint32_t)__cvta_generic_to_shared(
                Bs + (size_t)buf * BN * LDH + n * LDH + ch * 8);
            asm volatile("cp.async.cg.shared.global [%0], [%1], 16, %2;\n"
                         :: "r"(sa), "l"(gp), "r"(bytes));
        }
    };

    loadTiles2(0, 0);
    asm volatile("cp.async.commit_group;\n" ::: "memory");

    for (int it = 0; it < nIter; it++) {
        if (it + 1 < nIter) {
            loadTiles2((it + 1) & 1, (it + 1) * BK);
            asm volatile("cp.async.commit_group;\n" ::: "memory");
            asm volatile("cp.async.wait_group 1;\n" ::: "memory");
        } else {
            asm volatile("cp.async.wait_group 0;\n" ::: "memory");
        }
        __syncthreads();

        const int buf = it & 1;
        const __nv_bfloat16* Ab = As + (size_t)buf * BM * LDH;
        const __nv_bfloat16* Bb = Bs + (size_t)buf * BN * LDH;
#pragma unroll
        for (int kk = 0; kk < 2; kk++) {
            const int kb = kk * 16;
            uint32_t a[MT][4], b[NT][2];
#pragma unroll
            for (int mt = 0; mt < MT; mt++) {
                int r = warpM * 32 + mt * 16 + gid;
                a[mt][0] = *(const uint32_t*)(Ab + r * LDH + kb + 2 * tig);
                a[mt][1] = *(const uint32_t*)(Ab + (r + 8) * LDH + kb + 2 * tig);
                a[mt][2] = *(const uint32_t*)(Ab + r * LDH + kb + 2 * tig + 8);
                a[mt][3] = *(const uint32_t*)(Ab + (r + 8) * LDH + kb + 2 * tig + 8);
            }
#pragma unroll
            for (int nt = 0; nt < NT; nt++) {
                int c = warpN * 32 + nt * 8 + gid;
                b[nt][0] = *(const uint32_t*)(Bb + c * LDH + kb + 2 * tig);
                b[nt][1] = *(const uint32_t*)(Bb + c * LDH + kb + 2 * tig + 8);
            }
#pragma unroll
            for (int mt = 0; mt < MT; mt++)
#pragma unroll
                for (int nt = 0; nt < NT; nt++)
                    mma_bf16_16x8x16(acc[mt][nt], a[mt], b[nt]);
        }
        __syncthreads();
    }

    // epilogue: G2 = dinv * acc
#pragma unroll
    for (int mt = 0; mt < MT; mt++) {
        int r0 = rowBase + warpM * 32 + mt * 16 + gid;
        int r1 = r0 + 8;
        float s0 = (r0 < M) ? __ldg(&dinv[r0]) : 0.0f;
        float s1 = (r1 < M) ? __ldg(&dinv[r1]) : 0.0f;
#pragma unroll
        for (int nt = 0; nt < NT; nt++) {
            int c0 = warpN * 32 + nt * 8 + 2 * tig;
            if (r0 < M)
                *(float2*)(C + (size_t)r0 * F2 + c0) =
                    make_float2(s0 * acc[mt][nt][0], s0 * acc[mt][nt][1]);
            if (r1 < M)
                *(float2*)(C + (size_t)r1 * F2 + c0) =
                    make_float2(s1 * acc[mt][nt][2], s1 * acc[mt][nt][3]);
        }
    }
}

// ---------------- fused aggregation layer 2 ----------------
__global__ void k_agg2(const float2* __restrict__ G2_2, const int* __restrict__ rowptr,
                       const int* __restrict__ esrc, const float* __restrict__ dinv,
                       const float2* __restrict__ b2_2, float2* __restrict__ Z2) {
    int gw = (blockIdx.x * blockDim.x + threadIdx.x) >> 5;
    if (gw >= N_NODES) return;
    int lane = threadIdx.x & 31;
    const int j0 = rowptr[gw], j1 = rowptr[gw + 1];
    float2 acc = G2_2[(size_t)gw * 32 + lane];
    for (int j = j0; j < j1; j++) {
        int s = __ldg(&esrc[j]);
        float2 v = G2_2[(size_t)s * 32 + lane];
        acc.x += v.x; acc.y += v.y;
    }
    float di = dinv[gw];
    float2 b = b2_2[lane];
    Z2[(size_t)gw * 32 + lane] = make_float2(fmaf(di, acc.x, b.x), fmaf(di, acc.y, b.y));
}

// ---------------- decode ----------------
__global__ void k_decode(const float* __restrict__ Z, const int* __restrict__ src,
                         const int* __restrict__ dst, float* __restrict__ out, int E) {
    int gid = blockIdx.x * blockDim.x + threadIdx.x;
    int e = gid >> 3;
    if (e >= E) return;
    int t = gid & 7;
    int s = __ldg(&src[e]);
    int d = __ldg(&dst[e]);
    const float4* zs = (const float4*)(Z + (size_t)s * F2);
    const float4* zd = (const float4*)(Z + (size_t)d * F2);
    float sum = 0.0f;
#pragma unroll
    for (int i = t; i < 16; i += 8) {
        float4 a = zs[i];
        float4 b = zd[i];
        sum += a.x * b.x + a.y * b.y + a.z * b.z + a.w * b.w;
    }
#pragma unroll
    for (int off = 4; off; off >>= 1) sum += __shfl_down_sync(0xffffffffu, sum, off, 8);
    if (t == 0) out[e] = sum;
}

// ---------------- launch ----------------
extern "C" void kernel_launch(void* const* d_in, const int* in_sizes, int n_in,
                              void* d_out, int out_size) {
    const float* x  = (const float*)d_in[0];
    const int*   ei = (const int*)d_in[1];
    const float* W1 = (const float*)d_in[2];
    const float* b1 = (const float*)d_in[3];
    const float* W2 = (const float*)d_in[4];
    const float* b2 = (const float*)d_in[5];
    float* logits = (float*)d_out;

    const int E = in_sizes[1] / 2;
    const int M = N_NODES;
    const int* src = ei;
    const int* dst = ei + E;

    float *dinv, *G2, *Z;
    __nv_bfloat16 *Y, *W1T, *out1, *W2T;
    int *cnt, *rowptr, *cursor, *esrc;
    cudaGetSymbolAddress((void**)&dinv, g_dinv);
    cudaGetSymbolAddress((void**)&Y, g_Y);
    cudaGetSymbolAddress((void**)&W1T, g_W1T);
    cudaGetSymbolAddress((void**)&out1, g_out1);
    cudaGetSymbolAddress((void**)&W2T, g_W2T);
    cudaGetSymbolAddress((void**)&G2, g_G2);
    cudaGetSymbolAddress((void**)&Z, g_Z);
    cudaGetSymbolAddress((void**)&cnt, g_cnt);
    cudaGetSymbolAddress((void**)&rowptr, g_rowptr);
    cudaGetSymbolAddress((void**)&cursor, g_cursor);
    cudaGetSymbolAddress((void**)&esrc, g_esrc);

    // --- CSR build + dinv ---
    k_zero_int<<<(M + 255) / 256, 256>>>(cnt, M);
    k_hist<<<(E + 255) / 256, 256>>>(cnt, dst, E);
    k_scan<<<1, 1024>>>(cnt, rowptr, cursor, M);
    k_dinv<<<(M + 255) / 256, 256>>>(cnt, dinv, M);
    k_fill<<<(E + 255) / 256, 256>>>(cursor, esrc, src, dst, E);

    // --- weight prep: W1^T bf16, W2^T bf16 (zero-padded) ---
    {
        dim3 grid((F1 + 31) / 32, (F0 + 31) / 32);
        k_w1t<<<grid, dim3(32, 8)>>>(W1, W1T);
    }
    k_w2t<<<(F2 * F1P + 255) / 256, 256>>>(W2, W2T);

    // --- aggregate x first (conv linearity), bf16 output, 2 column passes ---
    k_aggx<<<M, 80>>>((const float4*)x, rowptr, esrc, dinv, Y, 0, 75);
    k_aggx<<<M, 80>>>((const float4*)x, rowptr, esrc, dinv, Y, 75, 75);

    // --- layer 1 GEMM (bf16): out1 = bf16(relu(Y @ W1 + b1)) ---
    {
        constexpr int SM1 = 2 * (128 * LDH + 128 * LDH) * 2;   // 40960 B
        cudaFuncSetAttribute((const void*)gemm1_bf16,
                             cudaFuncAttributeMaxDynamicSharedMemorySize, SM1);
        dim3 grid((F1P + 127) / 128, (M + 127) / 128);   // 5 x 391 (tile 4 covers pad)
        gemm1_bf16<<<grid, 256, SM1>>>(Y, W1T, out1, b1, M);
    }

    // --- layer 2 GEMM (bf16): G2 = dinv ⊙ (out1 @ W2) ---
    {
        constexpr int SM2 = 2 * (128 * LDH + 64 * LDH) * 2;    // 30720 B
        cudaFuncSetAttribute((const void*)gemm2_bf16,
                             cudaFuncAttributeMaxDynamicSharedMemorySize, SM2);
        dim3 grid(1, (M + 127) / 128);
        gemm2_bf16<<<grid, 256, SM2>>>(out1, W2T, G2, dinv, M);
    }
    k_agg2<<<(M * 32 + 255) / 256, 256>>>((const float2*)G2, rowptr, esrc, dinv,
                                          (const float2*)b2, (float2*)Z);

    // --- decode ---
    k_decode<<<(E * 8 + 255) / 256, 256>>>(Z, src, dst, logits, E);
}

// round 17
// speedup vs baseline: 5.6664x; 1.0619x over previous
#include <cuda_runtime.h>
#include <cuda_bf16.h>
#include <cstdint>

#define N_NODES 50000
#define E_MAX   400000
#define F0 600
#define F1 628
#define F1P 632   /* out1/W2T padded K (mult of 8), pad zeroed */
#define F2 64

// ---------------- scratch ----------------
__device__ float g_dinv[N_NODES];
__device__ __align__(16) __nv_bfloat16 g_Xh[(size_t)N_NODES * F0];    // dinv-prescaled x, bf16
__device__ __align__(16) __nv_bfloat16 g_Y[(size_t)N_NODES * F0];     // aggregated x (bf16)
__device__ __align__(16) __nv_bfloat16 g_W1T[(size_t)F1 * F0];        // W1^T bf16 [628][600]
__device__ __align__(16) __nv_bfloat16 g_out1[(size_t)N_NODES * F1P]; // relu out, bf16, padded
__device__ __align__(16) __nv_bfloat16 g_W2T[(size_t)F2 * F1P];       // W2^T bf16 [64][632]
__device__ float g_G2 [(size_t)N_NODES * F2];
__device__ float g_Z  [(size_t)N_NODES * F2];
__device__ int   g_cnt[N_NODES];
__device__ int   g_rowptr[N_NODES + 1];
__device__ int   g_cursor[N_NODES];
__device__ int   g_esrc[E_MAX];

// ---------------- helpers ----------------
__device__ __forceinline__ void mma_bf16_16x8x16(float* d, const uint32_t* a,
                                                 const uint32_t* b) {
    asm volatile(
        "mma.sync.aligned.m16n8k16.row.col.f32.bf16.bf16.f32 "
        "{%0,%1,%2,%3}, {%4,%5,%6,%7}, {%8,%9}, {%0,%1,%2,%3};"
        : "+f"(d[0]), "+f"(d[1]), "+f"(d[2]), "+f"(d[3])
        : "r"(a[0]), "r"(a[1]), "r"(a[2]), "r"(a[3]), "r"(b[0]), "r"(b[1]));
}

// ---------------- CSR build ----------------
__global__ void k_zero_int(int* p, int n) {
    int i = blockIdx.x * blockDim.x + threadIdx.x;
    if (i < n) p[i] = 0;
}
__global__ void k_hist(int* cnt, const int* __restrict__ dst, int e) {
    int i = blockIdx.x * blockDim.x + threadIdx.x;
    if (i < e) atomicAdd(&cnt[dst[i]], 1);
}
__global__ void k_scan(const int* __restrict__ cnt, int* __restrict__ rowptr,
                       int* __restrict__ cursor, int n) {
    __shared__ int part[1024];
    int tid = threadIdx.x;
    int chunk = (n + 1023) / 1024;
    int base = tid * chunk;
    int s = 0;
    for (int i = 0; i < chunk; i++) {
        int idx = base + i;
        if (idx < n) s += cnt[idx];
    }
    part[tid] = s;
    __syncthreads();
    for (int off = 1; off < 1024; off <<= 1) {
        int v = (tid >= off) ? part[tid - off] : 0;
        __syncthreads();
        part[tid] += v;
        __syncthreads();
    }
    int excl = (tid == 0) ? 0 : part[tid - 1];
    for (int i = 0; i < chunk; i++) {
        int idx = base + i;
        if (idx < n) {
            rowptr[idx] = excl;
            cursor[idx] = excl;
            excl += cnt[idx];
        }
    }
    if (tid == 1023) rowptr[n] = part[1023];
}
__global__ void k_dinv(const int* __restrict__ cnt, float* __restrict__ dinv, int n) {
    int i = blockIdx.x * blockDim.x + threadIdx.x;
    if (i < n) dinv[i] = rsqrtf((float)cnt[i] + 1.0f);
}
__global__ void k_fill(int* cursor, int* esrc, const int* __restrict__ src,
                       const int* __restrict__ dst, int e) {
    int i = blockIdx.x * blockDim.x + threadIdx.x;
    if (i >= e) return;
    int pos = atomicAdd(&cursor[dst[i]], 1);
    esrc[pos] = src[i];
}

// ---------------- x -> bf16, pre-scaled by dinv[row] ----------------
// Xh[i][c] = bf16(dinv[i] * x[i][c]); 8 elems per thread (uint4 store).
__global__ void k_xh(const float4* __restrict__ X4, const float* __restrict__ dinv,
                     uint4* __restrict__ Xh4) {
    int i = blockIdx.x * blockDim.x + threadIdx.x;
    const int n8 = N_NODES * (F0 / 8);
    if (i >= n8) return;
    int row = i / (F0 / 8);
    float di = __ldg(&dinv[row]);
    float4 a = X4[(size_t)i * 2];
    float4 b = X4[(size_t)i * 2 + 1];
    __nv_bfloat162 h0 = __float22bfloat162_rn(make_float2(di * a.x, di * a.y));
    __nv_bfloat162 h1 = __float22bfloat162_rn(make_float2(di * a.z, di * a.w));
    __nv_bfloat162 h2 = __float22bfloat162_rn(make_float2(di * b.x, di * b.y));
    __nv_bfloat162 h3 = __float22bfloat162_rn(make_float2(di * b.z, di * b.w));
    uint4 w;
    w.x = *(uint32_t*)&h0; w.y = *(uint32_t*)&h1;
    w.z = *(uint32_t*)&h2; w.w = *(uint32_t*)&h3;
    Xh4[i] = w;
}

// ---------------- aggregate: Y[d] = bf16( dinv[d] * Σ Xh rows ) ----------------
// Xh prescaled by dinv[src]; self term included. Single pass (60 MB L2-resident).
// One block per node, 75 active threads x 8 cols.
__global__ void k_aggx(const uint4* __restrict__ Xh4, const int* __restrict__ rowptr,
                       const int* __restrict__ esrc, const float* __restrict__ dinv,
                       uint4* __restrict__ Y4) {
    const int d = blockIdx.x;
    const int t = threadIdx.x;
    if (t >= F0 / 8) return;                 // 75
    const int j0 = rowptr[d], j1 = rowptr[d + 1];
    const size_t stride = F0 / 8;
    float acc[8];
    {
        uint4 w = Xh4[(size_t)d * stride + t];   // self (already dinv[d]*x[d])
        float2 f0 = __bfloat1622float2(*(__nv_bfloat162*)&w.x);
        float2 f1 = __bfloat1622float2(*(__nv_bfloat162*)&w.y);
        float2 f2 = __bfloat1622float2(*(__nv_bfloat162*)&w.z);
        float2 f3 = __bfloat1622float2(*(__nv_bfloat162*)&w.w);
        acc[0] = f0.x; acc[1] = f0.y; acc[2] = f1.x; acc[3] = f1.y;
        acc[4] = f2.x; acc[5] = f2.y; acc[6] = f3.x; acc[7] = f3.y;
    }
    for (int j = j0; j < j1; j++) {
        int s = __ldg(&esrc[j]);
        uint4 w = Xh4[(size_t)s * stride + t];
        float2 f0 = __bfloat1622float2(*(__nv_bfloat162*)&w.x);
        float2 f1 = __bfloat1622float2(*(__nv_bfloat162*)&w.y);
        float2 f2 = __bfloat1622float2(*(__nv_bfloat162*)&w.z);
        float2 f3 = __bfloat1622float2(*(__nv_bfloat162*)&w.w);
        acc[0] += f0.x; acc[1] += f0.y; acc[2] += f1.x; acc[3] += f1.y;
        acc[4] += f2.x; acc[5] += f2.y; acc[6] += f3.x; acc[7] += f3.y;
    }
    float di = dinv[d];
    __nv_bfloat162 h0 = __float22bfloat162_rn(make_float2(di * acc[0], di * acc[1]));
    __nv_bfloat162 h1 = __float22bfloat162_rn(make_float2(di * acc[2], di * acc[3]));
    __nv_bfloat162 h2 = __float22bfloat162_rn(make_float2(di * acc[4], di * acc[5]));
    __nv_bfloat162 h3 = __float22bfloat162_rn(make_float2(di * acc[6], di * acc[7]));
    uint4 w;
    w.x = *(uint32_t*)&h0; w.y = *(uint32_t*)&h1;
    w.z = *(uint32_t*)&h2; w.w = *(uint32_t*)&h3;
    Y4[(size_t)d * stride + t] = w;
}

// ---------------- W1 transpose -> bf16, n-major [F1][F0] ----------------
__global__ void k_w1t(const float* __restrict__ W, __nv_bfloat16* __restrict__ WT) {
    __shared__ float t[32][33];
    int bx = blockIdx.x * 32;  // n
    int by = blockIdx.y * 32;  // k
    int x = threadIdx.x, y = threadIdx.y;
    for (int i = y; i < 32; i += 8) {
        int k = by + i, n = bx + x;
        t[i][x] = (k < F0 && n < F1) ? W[(size_t)k * F1 + n] : 0.0f;
    }
    __syncthreads();
    for (int i = y; i < 32; i += 8) {
        int n = bx + i, k = by + x;
        if (n < F1 && k < F0) WT[(size_t)n * F0 + k] = __float2bfloat16_rn(t[x][i]);
    }
}

// ---------------- W2 transpose -> bf16 [F2][F1P], zero-padded K tail ----------------
__global__ void k_w2t(const float* __restrict__ W2, __nv_bfloat16* __restrict__ WT) {
    int idx = blockIdx.x * blockDim.x + threadIdx.x;
    if (idx >= F2 * F1P) return;
    int n = idx / F1P;
    int k = idx - n * F1P;
    WT[idx] = (k < F1) ? __float2bfloat16_rn(W2[(size_t)k * F2 + n]) : __nv_bfloat16(0.0f);
}

// ---------------- GEMM1: bf16 mma, out1 = bf16(relu(Y @ W1 + b1)) ----------------
#define LDH 40
__global__ __launch_bounds__(256, 2)
void gemm1_bf16(const __nv_bfloat16* __restrict__ A,
                const __nv_bfloat16* __restrict__ BT,
                __nv_bfloat16* __restrict__ C, const float* __restrict__ bias, int M) {
    constexpr int BM = 128, BN = 128, BK = 32;
    constexpr int MT = 2, NT = 8;
    extern __shared__ __nv_bfloat16 smh[];
    __nv_bfloat16* As = smh;                     // [2][BM][LDH]
    __nv_bfloat16* Bs = smh + 2 * BM * LDH;      // [2][BN][LDH]

    const int tid = threadIdx.x;
    const int lane = tid & 31;
    const int warp = tid >> 5;
    const int warpM = warp >> 1;     // 0..3
    const int warpN = warp & 1;      // 0..1
    const int gid = lane >> 2;
    const int tig = lane & 3;
    const int rowBase = blockIdx.y * BM;
    const int colBase = blockIdx.x * BN;

    float acc[MT][NT][4];
#pragma unroll
    for (int i = 0; i < MT; i++)
#pragma unroll
        for (int j = 0; j < NT; j++)
#pragma unroll
            for (int q = 0; q < 4; q++) acc[i][j][q] = 0.0f;

    auto loadTiles = [&](int buf, int k0) {
#pragma unroll
        for (int i = 0; i < 2; i++) {
            int f = tid + i * 256;
            int row = f >> 2, ch = f & 3;
            int grow = min(rowBase + row, M - 1);
            int gk = min(k0 + ch * 8, F0 - 8);
            const __nv_bfloat16* gp = A + (size_t)grow * F0 + gk;
            uint32_t sa = (uint32_t)__cvta_generic_to_shared(
                As + (size_t)buf * BM * LDH + row * LDH + ch * 8);
            asm volatile("cp.async.cg.shared.global [%0], [%1], 16;\n"
                         :: "r"(sa), "l"(gp));
        }
#pragma unroll
        for (int i = 0; i < 2; i++) {
            int f = tid + i * 256;
            int n = f >> 2, ch = f & 3;
            int gn = colBase + n;
            int gk = k0 + ch * 8;
            int bytes = (gn < F1 && gk < F0) ? 16 : 0;
            const __nv_bfloat16* gp = BT + (size_t)min(gn, F1 - 1) * F0 + min(gk, F0 - 8);
            uint32_t sa = (uint32_t)__cvta_generic_to_shared(
                Bs + (size_t)buf * BN * LDH + n * LDH + ch * 8);
            asm volatile("cp.async.cg.shared.global [%0], [%1], 16, %2;\n"
                         :: "r"(sa), "l"(gp), "r"(bytes));
        }
    };

    const int nIter = (F0 + BK - 1) / BK;   // 19
    loadTiles(0, 0);
    asm volatile("cp.async.commit_group;\n" ::: "memory");

    for (int it = 0; it < nIter; it++) {
        if (it + 1 < nIter) {
            loadTiles((it + 1) & 1, (it + 1) * BK);
            asm volatile("cp.async.commit_group;\n" ::: "memory");
            asm volatile("cp.async.wait_group 1;\n" ::: "memory");
        } else {
            asm volatile("cp.async.wait_group 0;\n" ::: "memory");
        }
        __syncthreads();

        const int buf = it & 1;
        const __nv_bfloat16* Ab = As + (size_t)buf * BM * LDH;
        const __nv_bfloat16* Bb = Bs + (size_t)buf * BN * LDH;
#pragma unroll
        for (int kk = 0; kk < 2; kk++) {
            const int kb = kk * 16;
            uint32_t a[MT][4], b[NT][2];
#pragma unroll
            for (int mt = 0; mt < MT; mt++) {
                int r = warpM * 32 + mt * 16 + gid;
                a[mt][0] = *(const uint32_t*)(Ab + r * LDH + kb + 2 * tig);
                a[mt][1] = *(const uint32_t*)(Ab + (r + 8) * LDH + kb + 2 * tig);
                a[mt][2] = *(const uint32_t*)(Ab + r * LDH + kb + 2 * tig + 8);
                a[mt][3] = *(const uint32_t*)(Ab + (r + 8) * LDH + kb + 2 * tig + 8);
            }
#pragma unroll
            for (int nt = 0; nt < NT; nt++) {
                int c = warpN * 64 + nt * 8 + gid;
                b[nt][0] = *(const uint32_t*)(Bb + c * LDH + kb + 2 * tig);
                b[nt][1] = *(const uint32_t*)(Bb + c * LDH + kb + 2 * tig + 8);
            }
#pragma unroll
            for (int mt = 0; mt < MT; mt++)
#pragma unroll
                for (int nt = 0; nt < NT; nt++)
                    mma_bf16_16x8x16(acc[mt][nt], a[mt], b[nt]);
        }
        __syncthreads();
    }

    // epilogue: bias + relu -> bf16 out1 (stride F1P; pad cols zeroed)
#pragma unroll
    for (int mt = 0; mt < MT; mt++) {
        int r0 = rowBase + warpM * 32 + mt * 16 + gid;
        int r1 = r0 + 8;
#pragma unroll
        for (int nt = 0; nt < NT; nt++) {
            int c0 = colBase + warpN * 64 + nt * 8 + 2 * tig;
            if (c0 >= F1P) continue;
            float2 bb = (c0 < F1) ? *(const float2*)(bias + c0) : make_float2(0.f, 0.f);
            if (r0 < M) {
                float2 v = make_float2(0.f, 0.f);
                if (c0 < F1) {
                    v.x = fmaxf(acc[mt][nt][0] + bb.x, 0.0f);
                    v.y = fmaxf(acc[mt][nt][1] + bb.y, 0.0f);
                }
                __nv_bfloat162 h = __float22bfloat162_rn(v);
                *(uint32_t*)(C + (size_t)r0 * F1P + c0) = *(uint32_t*)&h;
            }
            if (r1 < M) {
                float2 v = make_float2(0.f, 0.f);
                if (c0 < F1) {
                    v.x = fmaxf(acc[mt][nt][2] + bb.x, 0.0f);
                    v.y = fmaxf(acc[mt][nt][3] + bb.y, 0.0f);
                }
                __nv_bfloat162 h = __float22bfloat162_rn(v);
                *(uint32_t*)(C + (size_t)r1 * F1P + c0) = *(uint32_t*)&h;
            }
        }
    }
}

// ---------------- GEMM2: bf16 mma, G2 = dinv ⊙ (out1 @ W2) ----------------
__global__ __launch_bounds__(256, 2)
void gemm2_bf16(const __nv_bfloat16* __restrict__ A,
                const __nv_bfloat16* __restrict__ BT,
                float* __restrict__ C, const float* __restrict__ dinv, int M) {
    constexpr int BM = 128, BN = 64, BK = 32;
    constexpr int MT = 2, NT = 4;
    extern __shared__ __nv_bfloat16 smh[];
    __nv_bfloat16* As = smh;                     // [2][BM][LDH]
    __nv_bfloat16* Bs = smh + 2 * BM * LDH;      // [2][BN][LDH]

    const int tid = threadIdx.x;
    const int lane = tid & 31;
    const int warp = tid >> 5;
    const int warpM = warp >> 1;
    const int warpN = warp & 1;
    const int gid = lane >> 2;
    const int tig = lane & 3;
    const int rowBase = blockIdx.y * BM;

    float acc[MT][NT][4];
#pragma unroll
    for (int i = 0; i < MT; i++)
#pragma unroll
        for (int j = 0; j < NT; j++)
#pragma unroll
            for (int q = 0; q < 4; q++) acc[i][j][q] = 0.0f;

    auto loadTiles = [&](int buf, int k0) {
#pragma unroll
        for (int i = 0; i < 2; i++) {
            int f = tid + i * 256;
            int row = f >> 2, ch = f & 3;
            int grow = min(rowBase + row, M - 1);
            int gk = k0 + ch * 8;
            int bytes = (gk < F1P) ? 16 : 0;
            const __nv_bfloat16* gp = A + (size_t)grow * F1P + min(gk, F1P - 8);
            uint32_t sa = (uint32_t)__cvta_generic_to_shared(
                As + (size_t)buf * BM * LDH + row * LDH + ch * 8);
            asm volatile("cp.async.cg.shared.global [%0], [%1], 16, %2;\n"
                         :: "r"(sa), "l"(gp), "r"(bytes));
        }
        {
            int n = tid >> 2, ch = tid & 3;
            int gk = k0 + ch * 8;
            int bytes = (gk < F1P) ? 16 : 0;
            const __nv_bfloat16* gp = BT + (size_t)n * F1P + min(gk, F1P - 8);
            uint32_t sa = (uint32_t)__cvta_generic_to_shared(
                Bs + (size_t)buf * BN * LDH + n * LDH + ch * 8);
            asm volatile("cp.async.cg.shared.global [%0], [%1], 16, %2;\n"
                         :: "r"(sa), "l"(gp), "r"(bytes));
        }
    };

    const int nIter = (F1P + BK - 1) / BK;   // 20; tail slots zfilled
    loadTiles(0, 0);
    asm volatile("cp.async.commit_group;\n" ::: "memory");

    for (int it = 0; it < nIter; it++) {
        if (it + 1 < nIter) {
            loadTiles((it + 1) & 1, (it + 1) * BK);
            asm volatile("cp.async.commit_group;\n" ::: "memory");
            asm volatile("cp.async.wait_group 1;\n" ::: "memory");
        } else {
            asm volatile("cp.async.wait_group 0;\n" ::: "memory");
        }
        __syncthreads();

        const int buf = it & 1;
        const __nv_bfloat16* Ab = As + (size_t)buf * BM * LDH;
        const __nv_bfloat16* Bb = Bs + (size_t)buf * BN * LDH;
#pragma unroll
        for (int kk = 0; kk < 2; kk++) {
            const int kb = kk * 16;
            uint32_t a[MT][4], b[NT][2];
#pragma unroll
            for (int mt = 0; mt < MT; mt++) {
                int r = warpM * 32 + mt * 16 + gid;
                a[mt][0] = *(const uint32_t*)(Ab + r * LDH + kb + 2 * tig);
                a[mt][1] = *(const uint32_t*)(Ab + (r + 8) * LDH + kb + 2 * tig);
                a[mt][2] = *(const uint32_t*)(Ab + r * LDH + kb + 2 * tig + 8);
                a[mt][3] = *(const uint32_t*)(Ab + (r + 8) * LDH + kb + 2 * tig + 8);
            }
#pragma unroll
            for (int nt = 0; nt < NT; nt++) {
                int c = warpN * 32 + nt * 8 + gid;
                b[nt][0] = *(const uint32_t*)(Bb + c * LDH + kb + 2 * tig);
                b[nt][1] = *(const uint32_t*)(Bb + c * LDH + kb + 2 * tig + 8);
            }
#pragma unroll
            for (int mt = 0; mt < MT; mt++)
#pragma unroll
                for (int nt = 0; nt < NT; nt++)
                    mma_bf16_16x8x16(acc[mt][nt], a[mt], b[nt]);
        }
        __syncthreads();
    }

#pragma unroll
    for (int mt = 0; mt < MT; mt++) {
        int r0 = rowBase + warpM * 32 + mt * 16 + gid;
        int r1 = r0 + 8;
        float s0 = (r0 < M) ? __ldg(&dinv[r0]) : 0.0f;
        float s1 = (r1 < M) ? __ldg(&dinv[r1]) : 0.0f;
#pragma unroll
        for (int nt = 0; nt < NT; nt++) {
            int c0 = warpN * 32 + nt * 8 + 2 * tig;
            if (r0 < M)
                *(float2*)(C + (size_t)r0 * F2 + c0) =
                    make_float2(s0 * acc[mt][nt][0], s0 * acc[mt][nt][1]);
            if (r1 < M)
                *(float2*)(C + (size_t)r1 * F2 + c0) =
                    make_float2(s1 * acc[mt][nt][2], s1 * acc[mt][nt][3]);
        }
    }
}

// ---------------- fused aggregation layer 2 ----------------
__global__ void k_agg2(const float2* __restrict__ G2_2, const int* __restrict__ rowptr,
                       const int* __restrict__ esrc, const float* __restrict__ dinv,
                       const float2* __restrict__ b2_2, float2* __restrict__ Z2) {
    int gw = (blockIdx.x * blockDim.x + threadIdx.x) >> 5;
    if (gw >= N_NODES) return;
    int lane = threadIdx.x & 31;
    const int j0 = rowptr[gw], j1 = rowptr[gw + 1];
    float2 acc = G2_2[(size_t)gw * 32 + lane];
    for (int j = j0; j < j1; j++) {
        int s = __ldg(&esrc[j]);
        float2 v = G2_2[(size_t)s * 32 + lane];
        acc.x += v.x; acc.y += v.y;
    }
    float di = dinv[gw];
    float2 b = b2_2[lane];
    Z2[(size_t)gw * 32 + lane] = make_float2(fmaf(di, acc.x, b.x), fmaf(di, acc.y, b.y));
}

// ---------------- decode ----------------
__global__ void k_decode(const float* __restrict__ Z, const int* __restrict__ src,
                         const int* __restrict__ dst, float* __restrict__ out, int E) {
    int gid = blockIdx.x * blockDim.x + threadIdx.x;
    int e = gid >> 3;
    if (e >= E) return;
    int t = gid & 7;
    int s = __ldg(&src[e]);
    int d = __ldg(&dst[e]);
    const float4* zs = (const float4*)(Z + (size_t)s * F2);
    const float4* zd = (const float4*)(Z + (size_t)d * F2);
    float sum = 0.0f;
#pragma unroll
    for (int i = t; i < 16; i += 8) {
        float4 a = zs[i];
        float4 b = zd[i];
        sum += a.x * b.x + a.y * b.y + a.z * b.z + a.w * b.w;
    }
#pragma unroll
    for (int off = 4; off; off >>= 1) sum += __shfl_down_sync(0xffffffffu, sum, off, 8);
    if (t == 0) out[e] = sum;
}

// ---------------- launch ----------------
extern "C" void kernel_launch(void* const* d_in, const int* in_sizes, int n_in,
                              void* d_out, int out_size) {
    const float* x  = (const float*)d_in[0];
    const int*   ei = (const int*)d_in[1];
    const float* W1 = (const float*)d_in[2];
    const float* b1 = (const float*)d_in[3];
    const float* W2 = (const float*)d_in[4];
    const float* b2 = (const float*)d_in[5];
    float* logits = (float*)d_out;

    const int E = in_sizes[1] / 2;
    const int M = N_NODES;
    const int* src = ei;
    const int* dst = ei + E;

    float *dinv, *G2, *Z;
    __nv_bfloat16 *Xh, *Y, *W1T, *out1, *W2T;
    int *cnt, *rowptr, *cursor, *esrc;
    cudaGetSymbolAddress((void**)&dinv, g_dinv);
    cudaGetSymbolAddress((void**)&Xh, g_Xh);
    cudaGetSymbolAddress((void**)&Y, g_Y);
    cudaGetSymbolAddress((void**)&W1T, g_W1T);
    cudaGetSymbolAddress((void**)&out1, g_out1);
    cudaGetSymbolAddress((void**)&W2T, g_W2T);
    cudaGetSymbolAddress((void**)&G2, g_G2);
    cudaGetSymbolAddress((void**)&Z, g_Z);
    cudaGetSymbolAddress((void**)&cnt, g_cnt);
    cudaGetSymbolAddress((void**)&rowptr, g_rowptr);
    cudaGetSymbolAddress((void**)&cursor, g_cursor);
    cudaGetSymbolAddress((void**)&esrc, g_esrc);

    // --- CSR build + dinv ---
    k_zero_int<<<(M + 255) / 256, 256>>>(cnt, M);
    k_hist<<<(E + 255) / 256, 256>>>(cnt, dst, E);
    k_scan<<<1, 1024>>>(cnt, rowptr, cursor, M);
    k_dinv<<<(M + 255) / 256, 256>>>(cnt, dinv, M);
    k_fill<<<(E + 255) / 256, 256>>>(cursor, esrc, src, dst, E);

    // --- weight prep ---
    {
        dim3 grid((F1 + 31) / 32, (F0 + 31) / 32);
        k_w1t<<<grid, dim3(32, 8)>>>(W1, W1T);
    }
    k_w2t<<<(F2 * F1P + 255) / 256, 256>>>(W2, W2T);

    // --- Xh = bf16(dinv ⊙ x) ---
    {
        int n8 = M * (F0 / 8);
        k_xh<<<(n8 + 255) / 256, 256>>>((const float4*)x, dinv, (uint4*)Xh);
    }
    // --- aggregate (single pass, bf16 gather) ---
    k_aggx<<<M, 80>>>((const uint4*)Xh, rowptr, esrc, dinv, (uint4*)Y);

    // --- layer 1 GEMM (bf16): out1 = bf16(relu(Y @ W1 + b1)) ---
    {
        constexpr int SM1 = 2 * (128 * LDH + 128 * LDH) * 2;   // 40960 B
        cudaFuncSetAttribute((const void*)gemm1_bf16,
                             cudaFuncAttributeMaxDynamicSharedMemorySize, SM1);
        dim3 grid((F1P + 127) / 128, (M + 127) / 128);
        gemm1_bf16<<<grid, 256, SM1>>>(Y, W1T, out1, b1, M);
    }

    // --- layer 2 GEMM (bf16): G2 = dinv ⊙ (out1 @ W2) ---
    {
        constexpr int SM2 = 2 * (128 * LDH + 64 * LDH) * 2;    // 30720 B
        cudaFuncSetAttribute((const void*)gemm2_bf16,
                             cudaFuncAttributeMaxDynamicSharedMemorySize, SM2);
        dim3 grid(1, (M + 127) / 128);
        gemm2_bf16<<<grid, 256, SM2>>>(out1, W2T, G2, dinv, M);
    }
    k_agg2<<<(M * 32 + 255) / 256, 256>>>((const float2*)G2, rowptr, esrc, dinv,
                                          (const float2*)b2, (float2*)Z);

    // --- decode ---
    k_decode<<<(E * 8 + 255) / 256, 256>>>(Z, src, dst, logits, E);
}